// round 1
// baseline (speedup 1.0000x reference)
#include <cuda_runtime.h>
#include <math.h>

#define NPTS  32768
#define NEDGE 786432
#define CIN   16
#define CMID  64
#define COUT  64
#define KMAX  64

// Scratch: P[n][c*64+m], 32768 x 1024 f32 (134 MB). __device__ global (no alloc allowed).
__device__ float g_P[(size_t)NPTS * (CIN * CMID)];

__device__ __forceinline__ float celu1(float x) {
    // jax.nn.celu with alpha=1: x>0 ? x : exp(x)-1
    return x > 0.0f ? x : expm1f(x);
}

__device__ __forceinline__ int lower_bound_dev(const int* __restrict__ a, int len, int v) {
    int lo = 0, hi = len;
    while (lo < hi) {
        int mid = (lo + hi) >> 1;
        if (__ldg(a + mid) < v) lo = mid + 1; else hi = mid;
    }
    return lo;
}

// ---------------------------------------------------------------------------
// Kernel 1: one CTA (64 threads) per output point.
// Thread m owns output column m of the per-point product P[16][64].
// Stage 1 (per-edge, one thread per edge): h_e[16] = celu(d_e @ W1), x_e[16]
// Stage 2 (per-thread m, loop over edges): M = celu(h_e . W2[:,m]);
//                                          P[c] += x_e[c] * M
// ---------------------------------------------------------------------------
__global__ __launch_bounds__(64) void edge_kernel(
    const float* __restrict__ x_in,     // [N,16]
    const float* __restrict__ pos_in,   // [N,3]
    const float* __restrict__ pos_out,  // [N,3]
    const int*   __restrict__ in_index, // [E]
    const int*   __restrict__ out_index,// [E] sorted
    const float* __restrict__ W1,       // [3,16]
    const float* __restrict__ W2)       // [16,64]
{
    const int n = blockIdx.x;
    const int m = threadIdx.x;  // 0..63

    __shared__ __align__(16) float sW1[48];
    __shared__ __align__(16) float s_h[KMAX][20];  // pad 20: 80B rows, 16B aligned
    __shared__ __align__(16) float s_x[KMAX][20];

    if (m < 48) sW1[m] = W1[m];

    // W2 column for this thread (coalesced across m)
    float w2c[CIN];
#pragma unroll
    for (int c = 0; c < CIN; c++) w2c[c] = W2[c * CMID + m];

    // contiguous edge range of point n (out_index sorted)
    const int start = lower_bound_dev(out_index, NEDGE, n);
    const int end   = lower_bound_dev(out_index, NEDGE, n + 1);
    const int cnt   = end - start;
    const int nl    = cnt < KMAX ? cnt : KMAX;  // slots >= K dropped (ref semantics)

    const float po0 = pos_out[3 * n + 0];
    const float po1 = pos_out[3 * n + 1];
    const float po2 = pos_out[3 * n + 2];

    __syncthreads();  // sW1 ready

    if (m < nl) {
        const int e = start + m;
        const int i = __ldg(in_index + e);
        const float d0 = __ldg(pos_in + 3 * i + 0) - po0;
        const float d1 = __ldg(pos_in + 3 * i + 1) - po1;
        const float d2 = __ldg(pos_in + 3 * i + 2) - po2;
#pragma unroll
        for (int c = 0; c < CIN; c++) {
            float a = fmaf(d0, sW1[c], fmaf(d1, sW1[16 + c], d2 * sW1[32 + c]));
            s_h[m][c] = celu1(a);
        }
        const float4* xr = (const float4*)(x_in + (size_t)i * CIN);
#pragma unroll
        for (int q = 0; q < 4; q++) {
            float4 v = __ldg(xr + q);
            s_x[m][4 * q + 0] = v.x;
            s_x[m][4 * q + 1] = v.y;
            s_x[m][4 * q + 2] = v.z;
            s_x[m][4 * q + 3] = v.w;
        }
    }
    __syncthreads();

    float P[CIN];
#pragma unroll
    for (int c = 0; c < CIN; c++) P[c] = 0.0f;

    for (int e = 0; e < nl; e++) {
        const float4* hp = (const float4*)s_h[e];  // broadcast LDS.128
        const float4* xp = (const float4*)s_x[e];
        float4 h0 = hp[0], h1 = hp[1], h2 = hp[2], h3 = hp[3];
        float acc;
        acc = h0.x * w2c[0];
        acc = fmaf(h0.y, w2c[1], acc);
        acc = fmaf(h0.z, w2c[2], acc);
        acc = fmaf(h0.w, w2c[3], acc);
        acc = fmaf(h1.x, w2c[4], acc);
        acc = fmaf(h1.y, w2c[5], acc);
        acc = fmaf(h1.z, w2c[6], acc);
        acc = fmaf(h1.w, w2c[7], acc);
        acc = fmaf(h2.x, w2c[8], acc);
        acc = fmaf(h2.y, w2c[9], acc);
        acc = fmaf(h2.z, w2c[10], acc);
        acc = fmaf(h2.w, w2c[11], acc);
        acc = fmaf(h3.x, w2c[12], acc);
        acc = fmaf(h3.y, w2c[13], acc);
        acc = fmaf(h3.z, w2c[14], acc);
        acc = fmaf(h3.w, w2c[15], acc);
        const float M = celu1(acc);
        float4 x0 = xp[0], x1 = xp[1], x2 = xp[2], x3 = xp[3];
        P[0]  = fmaf(x0.x, M, P[0]);
        P[1]  = fmaf(x0.y, M, P[1]);
        P[2]  = fmaf(x0.z, M, P[2]);
        P[3]  = fmaf(x0.w, M, P[3]);
        P[4]  = fmaf(x1.x, M, P[4]);
        P[5]  = fmaf(x1.y, M, P[5]);
        P[6]  = fmaf(x1.z, M, P[6]);
        P[7]  = fmaf(x1.w, M, P[7]);
        P[8]  = fmaf(x2.x, M, P[8]);
        P[9]  = fmaf(x2.y, M, P[9]);
        P[10] = fmaf(x2.z, M, P[10]);
        P[11] = fmaf(x2.w, M, P[11]);
        P[12] = fmaf(x3.x, M, P[12]);
        P[13] = fmaf(x3.y, M, P[13]);
        P[14] = fmaf(x3.z, M, P[14]);
        P[15] = fmaf(x3.w, M, P[15]);
    }

    const float inv = (cnt > 0) ? (1.0f / (float)cnt) : 0.0f;
    float* dst = g_P + (size_t)n * (CIN * CMID) + m;
#pragma unroll
    for (int c = 0; c < CIN; c++) dst[c * CMID] = P[c] * inv;
}

// ---------------------------------------------------------------------------
// Kernel 2: out[32768,64] = g_P[32768,1024] @ W3[1024,64] + b3
// BM=64, BN=64, BK=16, 256 threads, 4x4 micro-tile per thread.
// ---------------------------------------------------------------------------
#define BM 64
#define BN 64
#define BK 16

__global__ __launch_bounds__(256) void gemm_kernel(
    const float* __restrict__ W3,  // [1024,64]
    const float* __restrict__ b3,  // [64]
    float* __restrict__ out)       // [32768,64]
{
    __shared__ __align__(16) float As[BK][BM + 4];  // A tile, transposed (k-major)
    __shared__ __align__(16) float Bs[BK][BN];

    const int tid = threadIdx.x;
    const int tx = tid & 15;       // col group 0..15
    const int ty = tid >> 4;       // row group 0..15
    const int rowBase = blockIdx.x * BM;

    float acc[4][4];
#pragma unroll
    for (int i = 0; i < 4; i++)
#pragma unroll
        for (int j = 0; j < 4; j++) acc[i][j] = 0.0f;

    // A-load mapping: 256 threads x float4 = 1024 floats = 64 rows x 16 k
    const int ar = tid >> 2;          // row 0..63
    const int ak = (tid & 3) * 4;     // k 0,4,8,12
    // B-load mapping: 256 threads x float4 = 16 rows x 64 cols
    const int br = tid >> 4;          // k row 0..15
    const int bc = (tid & 15) * 4;    // col

    const float* A = g_P;

    for (int kt = 0; kt < CIN * CMID; kt += BK) {
        {
            float4 v = *(const float4*)(A + (size_t)(rowBase + ar) * 1024 + kt + ak);
            As[ak + 0][ar] = v.x;
            As[ak + 1][ar] = v.y;
            As[ak + 2][ar] = v.z;
            As[ak + 3][ar] = v.w;
        }
        {
            float4 v = __ldg((const float4*)(W3 + (size_t)(kt + br) * COUT + bc));
            *(float4*)&Bs[br][bc] = v;
        }
        __syncthreads();
#pragma unroll
        for (int k = 0; k < BK; k++) {
            float4 a = *(const float4*)&As[k][ty * 4];
            float4 b = *(const float4*)&Bs[k][tx * 4];
            acc[0][0] = fmaf(a.x, b.x, acc[0][0]);
            acc[0][1] = fmaf(a.x, b.y, acc[0][1]);
            acc[0][2] = fmaf(a.x, b.z, acc[0][2]);
            acc[0][3] = fmaf(a.x, b.w, acc[0][3]);
            acc[1][0] = fmaf(a.y, b.x, acc[1][0]);
            acc[1][1] = fmaf(a.y, b.y, acc[1][1]);
            acc[1][2] = fmaf(a.y, b.z, acc[1][2]);
            acc[1][3] = fmaf(a.y, b.w, acc[1][3]);
            acc[2][0] = fmaf(a.z, b.x, acc[2][0]);
            acc[2][1] = fmaf(a.z, b.y, acc[2][1]);
            acc[2][2] = fmaf(a.z, b.z, acc[2][2]);
            acc[2][3] = fmaf(a.z, b.w, acc[2][3]);
            acc[3][0] = fmaf(a.w, b.x, acc[3][0]);
            acc[3][1] = fmaf(a.w, b.y, acc[3][1]);
            acc[3][2] = fmaf(a.w, b.z, acc[3][2]);
            acc[3][3] = fmaf(a.w, b.w, acc[3][3]);
        }
        __syncthreads();
    }

    float bb0 = b3[tx * 4 + 0];
    float bb1 = b3[tx * 4 + 1];
    float bb2 = b3[tx * 4 + 2];
    float bb3v = b3[tx * 4 + 3];
#pragma unroll
    for (int i = 0; i < 4; i++) {
        float4 v;
        v.x = acc[i][0] + bb0;
        v.y = acc[i][1] + bb1;
        v.z = acc[i][2] + bb2;
        v.w = acc[i][3] + bb3v;
        *(float4*)(out + (size_t)(rowBase + ty * 4 + i) * COUT + tx * 4) = v;
    }
}

extern "C" void kernel_launch(void* const* d_in, const int* in_sizes, int n_in,
                              void* d_out, int out_size) {
    const float* x_in      = (const float*)d_in[0];
    const float* pos_in    = (const float*)d_in[1];
    const float* pos_out   = (const float*)d_in[2];
    const int*   in_index  = (const int*)d_in[3];
    const int*   out_index = (const int*)d_in[4];
    const float* W1        = (const float*)d_in[5];
    const float* W2        = (const float*)d_in[6];
    const float* W3        = (const float*)d_in[7];
    const float* b3        = (const float*)d_in[8];
    float* out = (float*)d_out;

    edge_kernel<<<NPTS, 64>>>(x_in, pos_in, pos_out, in_index, out_index, W1, W2);
    gemm_kernel<<<NPTS / BM, 256>>>(W3, b3, out);
}

// round 3
// speedup vs baseline: 1.7323x; 1.7323x over previous
#include <cuda_runtime.h>
#include <cuda_bf16.h>
#include <math.h>
#include <stdint.h>

#define NPTS  32768
#define NEDGE 786432
#define CIN   16
#define CMID  64
#define COUT  64
#define KMAX  64

// ---------------- device scratch (no allocs allowed) ----------------
__device__ __nv_bfloat16 g_P_hi[(size_t)NPTS * 1024];   // P split hi, [N,1024]
__device__ __nv_bfloat16 g_P_lo[(size_t)NPTS * 1024];   // P split lo
__device__ __nv_bfloat16 g_W3T_hi[COUT * 1024];         // W3^T split, [64][1024]
__device__ __nv_bfloat16 g_W3T_lo[COUT * 1024];
__device__ int g_start[NPTS + 1];

__device__ __forceinline__ float celu_fast(float x) {
    return x > 0.0f ? x : (__expf(x) - 1.0f);
}
__device__ __forceinline__ uint32_t smem_u32(const void* p) {
    uint32_t a;
    asm("{ .reg .u64 t; cvta.to.shared.u64 t, %1; cvt.u32.u64 %0, t; }" : "=r"(a) : "l"(p));
    return a;
}
__device__ __forceinline__ void cp16(uint32_t dst, const void* src) {
    asm volatile("cp.async.cg.shared.global [%0], [%1], 16;" :: "r"(dst), "l"(src) : "memory");
}
#define CP_COMMIT() asm volatile("cp.async.commit_group;" ::: "memory")
#define CP_WAIT(n)  asm volatile("cp.async.wait_group %0;" :: "n"(n) : "memory")

#define LDMATRIX_X4(r0, r1, r2, r3, addr) \
    asm volatile("ldmatrix.sync.aligned.m8n8.x4.shared.b16 {%0,%1,%2,%3}, [%4];" \
                 : "=r"(r0), "=r"(r1), "=r"(r2), "=r"(r3) : "r"(addr))

#define MMA_BF16(C, A, B0, B1) \
    asm volatile("mma.sync.aligned.m16n8k16.row.col.f32.bf16.bf16.f32 " \
        "{%0,%1,%2,%3}, {%4,%5,%6,%7}, {%8,%9}, {%0,%1,%2,%3};" \
        : "+f"((C)[0]), "+f"((C)[1]), "+f"((C)[2]), "+f"((C)[3]) \
        : "r"((A)[0]), "r"((A)[1]), "r"((A)[2]), "r"((A)[3]), "r"(B0), "r"(B1))

// ---------------------------------------------------------------------------
// Kernel A: segment offsets (boundary detection on sorted out_index)
// ---------------------------------------------------------------------------
__global__ void offsets_kernel(const int* __restrict__ oi) {
    int e = blockIdx.x * 256 + threadIdx.x;
    if (e >= NEDGE) return;
    int v = oi[e];
    if (e == 0) {
        for (int n = 0; n <= v; n++) g_start[n] = 0;
    } else {
        int p = oi[e - 1];
        for (int n = p + 1; n <= v; n++) g_start[n] = e;
    }
    if (e == NEDGE - 1) {
        for (int n = v + 1; n <= NPTS; n++) g_start[n] = NEDGE;
    }
}

// ---------------------------------------------------------------------------
// Kernel B: W3 transpose + bf16 hi/lo split
// ---------------------------------------------------------------------------
__global__ void prep_w3_kernel(const float* __restrict__ W3) {
    int t = blockIdx.x * 256 + threadIdx.x;   // 65536
    int k = t >> 6, n = t & 63;
    float v = W3[t];
    __nv_bfloat16 hi = __float2bfloat16_rn(v);
    __nv_bfloat16 lo = __float2bfloat16_rn(v - __bfloat162float(hi));
    g_W3T_hi[n * 1024 + k] = hi;
    g_W3T_lo[n * 1024 + k] = lo;
}

// ---------------------------------------------------------------------------
// Kernel C: edge phase. Warp per point; lane owns columns m and m+32.
// ---------------------------------------------------------------------------
__global__ __launch_bounds__(128) void edge_kernel(
    const float* __restrict__ x_in,
    const float* __restrict__ pos_in,
    const float* __restrict__ pos_out,
    const int*   __restrict__ in_index,
    const float* __restrict__ W1,
    const float* __restrict__ W2)
{
    __shared__ float sW1[48];
    __shared__ float s_h[4][KMAX][16];
    __shared__ float s_x[4][KMAX][16];

    const int tid = threadIdx.x;
    if (tid < 48) sW1[tid] = W1[tid];
    __syncthreads();

    const int w    = tid >> 5;
    const int lane = tid & 31;
    const int n    = blockIdx.x * 4 + w;

    const int start = g_start[n];
    const int cnt   = g_start[n + 1] - start;
    const int nl    = cnt < KMAX ? cnt : KMAX;

    const float po0 = __ldg(pos_out + 3 * n + 0);
    const float po1 = __ldg(pos_out + 3 * n + 1);
    const float po2 = __ldg(pos_out + 3 * n + 2);

    const int half = lane >> 4;
    const int c    = lane & 15;
    for (int base = 0; base < nl; base += 2) {
        int e = base + half;
        if (e < nl) {
            int idx  = __ldg(in_index + start + e);
            float d0 = __ldg(pos_in + 3 * idx + 0) - po0;
            float d1 = __ldg(pos_in + 3 * idx + 1) - po1;
            float d2 = __ldg(pos_in + 3 * idx + 2) - po2;
            float a  = fmaf(d0, sW1[c], fmaf(d1, sW1[16 + c], d2 * sW1[32 + c]));
            s_h[w][e][c] = celu_fast(a);
            s_x[w][e][c] = __ldg(x_in + (size_t)idx * CIN + c);
        }
    }
    __syncwarp();

    const int m = lane;
    float w2a[16], w2b[16];
#pragma unroll
    for (int j = 0; j < 16; j++) {
        w2a[j] = __ldg(W2 + j * CMID + m);
        w2b[j] = __ldg(W2 + j * CMID + m + 32);
    }

    float Pa[16], Pb[16];
#pragma unroll
    for (int j = 0; j < 16; j++) { Pa[j] = 0.0f; Pb[j] = 0.0f; }

    for (int e = 0; e < nl; e++) {
        const float4* hp = (const float4*)s_h[w][e];
        float hh[16];
#pragma unroll
        for (int q = 0; q < 4; q++) {
            float4 v = hp[q];
            hh[4 * q + 0] = v.x; hh[4 * q + 1] = v.y;
            hh[4 * q + 2] = v.z; hh[4 * q + 3] = v.w;
        }
        float a1 = hh[0] * w2a[0];
        float a2 = hh[0] * w2b[0];
#pragma unroll
        for (int j = 1; j < 16; j++) {
            a1 = fmaf(hh[j], w2a[j], a1);
            a2 = fmaf(hh[j], w2b[j], a2);
        }
        float M1 = celu_fast(a1);
        float M2 = celu_fast(a2);

        const float4* xp = (const float4*)s_x[w][e];
        float xx[16];
#pragma unroll
        for (int q = 0; q < 4; q++) {
            float4 v = xp[q];
            xx[4 * q + 0] = v.x; xx[4 * q + 1] = v.y;
            xx[4 * q + 2] = v.z; xx[4 * q + 3] = v.w;
        }
#pragma unroll
        for (int j = 0; j < 16; j++) {
            Pa[j] = fmaf(xx[j], M1, Pa[j]);
            Pb[j] = fmaf(xx[j], M2, Pb[j]);
        }
    }

    const float inv = (cnt > 0) ? (1.0f / (float)cnt) : 0.0f;
    __nv_bfloat16* dh = g_P_hi + (size_t)n * 1024;
    __nv_bfloat16* dl = g_P_lo + (size_t)n * 1024;
#pragma unroll
    for (int j = 0; j < 16; j++) {
        float va = Pa[j] * inv;
        float vb = Pb[j] * inv;
        __nv_bfloat16 ha = __float2bfloat16_rn(va);
        __nv_bfloat16 hb = __float2bfloat16_rn(vb);
        dh[j * CMID + m]      = ha;
        dh[j * CMID + m + 32] = hb;
        dl[j * CMID + m]      = __float2bfloat16_rn(va - __bfloat162float(ha));
        dl[j * CMID + m + 32] = __float2bfloat16_rn(vb - __bfloat162float(hb));
    }
}

// ---------------------------------------------------------------------------
// Kernel D: out[32768,64] = P[32768,1024] @ W3[1024,64] + b3
// mma.sync m16n8k16 bf16, 2-term split (3 products), cp.async double-buffer.
// CTA: 128 threads (4 warps), M-tile 128, warp = 32 rows. 256 CTAs.
// ---------------------------------------------------------------------------
#define PITCH_B 80          // smem row pitch bytes (40 bf16) — conflict-free ldmatrix
#define OFF_AHI 0
#define OFF_ALO 10240       // 128*80
#define OFF_BHI 20480
#define OFF_BLO 25600       // +64*80
#define STAGE_BYTES 30720
#define GEMM_SMEM (2 * STAGE_BYTES)

__global__ __launch_bounds__(128) void gemm_mma(
    const float* __restrict__ b3,
    float* __restrict__ out)
{
    extern __shared__ char dsm[];
    const uint32_t sbase = smem_u32(dsm);

    const int tid  = threadIdx.x;
    const int warp = tid >> 5;
    const int lane = tid & 31;
    const int ctaM = blockIdx.x * 128;
    const int warpM = warp * 32;

    const char* Ahi_g = (const char*)(g_P_hi + (size_t)ctaM * 1024);
    const char* Alo_g = (const char*)(g_P_lo + (size_t)ctaM * 1024);
    const char* Bhi_g = (const char*)g_W3T_hi;
    const char* Blo_g = (const char*)g_W3T_lo;

    // cp.async load of one k-chunk (32 k-values) into stage s
    auto issue_loads = [&](int kt, int s) {
        uint32_t base = sbase + s * STAGE_BYTES;
        const int kb = kt * 64;  // byte offset of chunk within 2048-byte row
#pragma unroll
        for (int i = 0; i < 4; i++) {
            int idx = tid + i * 128;           // 0..511
            int row = idx >> 2, seg = idx & 3;
            uint32_t d = base + OFF_AHI + row * PITCH_B + seg * 16;
            cp16(d, Ahi_g + (size_t)row * 2048 + kb + seg * 16);
            cp16(d + (OFF_ALO - OFF_AHI), Alo_g + (size_t)row * 2048 + kb + seg * 16);
        }
#pragma unroll
        for (int i = 0; i < 2; i++) {
            int idx = tid + i * 128;           // 0..255
            int row = idx >> 2, seg = idx & 3;
            uint32_t d = base + OFF_BHI + row * PITCH_B + seg * 16;
            cp16(d, Bhi_g + (size_t)row * 2048 + kb + seg * 16);
            cp16(d + (OFF_BLO - OFF_BHI), Blo_g + (size_t)row * 2048 + kb + seg * 16);
        }
    };

    float C[2][8][4];
#pragma unroll
    for (int mt = 0; mt < 2; mt++)
#pragma unroll
        for (int nt = 0; nt < 8; nt++)
#pragma unroll
            for (int q = 0; q < 4; q++) C[mt][nt][q] = 0.0f;

    // ldmatrix lane-address components
    const uint32_t aRow   = warpM + (lane & 15);
    const uint32_t aColB  = ((lane >> 4) & 1) * 16;            // +8 cols -> +16 bytes
    const uint32_t bRow   = (lane & 7) + ((lane & 16) ? 8 : 0);
    const uint32_t bColB  = ((lane & 8) ? 16 : 0);

    issue_loads(0, 0);
    CP_COMMIT();

    for (int kt = 0; kt < 32; kt++) {
        const int s = kt & 1;
        if (kt + 1 < 32) {
            issue_loads(kt + 1, 1 - s);
            CP_COMMIT();
            CP_WAIT(1);
        } else {
            CP_WAIT(0);
        }
        __syncthreads();

        const uint32_t base = sbase + s * STAGE_BYTES;
#pragma unroll
        for (int ks = 0; ks < 2; ks++) {
            const uint32_t kOffB = ks * 32;  // 16 bf16 = 32 bytes
            uint32_t ah[2][4], al[2][4];
#pragma unroll
            for (int mt = 0; mt < 2; mt++) {
                uint32_t addr = base + OFF_AHI + (aRow + mt * 16) * PITCH_B + kOffB + aColB;
                LDMATRIX_X4(ah[mt][0], ah[mt][1], ah[mt][2], ah[mt][3], addr);
                addr += (OFF_ALO - OFF_AHI);
                LDMATRIX_X4(al[mt][0], al[mt][1], al[mt][2], al[mt][3], addr);
            }
#pragma unroll
            for (int p = 0; p < 4; p++) {      // n-tile pairs (2p, 2p+1)
                uint32_t bh0, bh1, bh2, bh3, bl0, bl1, bl2, bl3;
                uint32_t addr = base + OFF_BHI + (p * 16 + bRow) * PITCH_B + kOffB + bColB;
                LDMATRIX_X4(bh0, bh1, bh2, bh3, addr);
                addr += (OFF_BLO - OFF_BHI);
                LDMATRIX_X4(bl0, bl1, bl2, bl3, addr);
#pragma unroll
                for (int mt = 0; mt < 2; mt++) {
                    MMA_BF16(C[mt][2 * p],     ah[mt], bh0, bh1);
                    MMA_BF16(C[mt][2 * p],     al[mt], bh0, bh1);
                    MMA_BF16(C[mt][2 * p],     ah[mt], bl0, bl1);
                    MMA_BF16(C[mt][2 * p + 1], ah[mt], bh2, bh3);
                    MMA_BF16(C[mt][2 * p + 1], al[mt], bh2, bh3);
                    MMA_BF16(C[mt][2 * p + 1], ah[mt], bl2, bl3);
                }
            }
        }
        __syncthreads();
    }

    // epilogue
    const int g = lane >> 2;
    const int q2 = (lane & 3) * 2;
#pragma unroll
    for (int mt = 0; mt < 2; mt++) {
        const int row = ctaM + warpM + mt * 16 + g;
#pragma unroll
        for (int nt = 0; nt < 8; nt++) {
            const int col = nt * 8 + q2;
            float2 bb = *(const float2*)(b3 + col);
            float2 v0, v1;
            v0.x = C[mt][nt][0] + bb.x;
            v0.y = C[mt][nt][1] + bb.y;
            v1.x = C[mt][nt][2] + bb.x;
            v1.y = C[mt][nt][3] + bb.y;
            *(float2*)(out + (size_t)row * COUT + col) = v0;
            *(float2*)(out + (size_t)(row + 8) * COUT + col) = v1;
        }
    }
}

// ---------------------------------------------------------------------------
extern "C" void kernel_launch(void* const* d_in, const int* in_sizes, int n_in,
                              void* d_out, int out_size) {
    const float* x_in      = (const float*)d_in[0];
    const float* pos_in    = (const float*)d_in[1];
    const float* pos_out   = (const float*)d_in[2];
    const int*   in_index  = (const int*)d_in[3];
    const int*   out_index = (const int*)d_in[4];
    const float* W1        = (const float*)d_in[5];
    const float* W2        = (const float*)d_in[6];
    const float* W3        = (const float*)d_in[7];
    const float* b3        = (const float*)d_in[8];
    float* out = (float*)d_out;

    cudaFuncSetAttribute(gemm_mma, cudaFuncAttributeMaxDynamicSharedMemorySize, GEMM_SMEM);

    offsets_kernel<<<(NEDGE + 255) / 256, 256>>>(out_index);
    prep_w3_kernel<<<(1024 * 64) / 256, 256>>>(W3);
    edge_kernel<<<NPTS / 4, 128>>>(x_in, pos_in, pos_out, in_index, W1, W2);
    gemm_mma<<<NPTS / 128, 128, GEMM_SMEM>>>(b3, out);
}

// round 4
// speedup vs baseline: 1.7422x; 1.0057x over previous
#include <cuda_runtime.h>
#include <cuda_bf16.h>
#include <math.h>
#include <stdint.h>

#define NPTS  32768
#define NEDGE 786432
#define CIN   16
#define CMID  64
#define COUT  64
#define KMAX  64

// ---------------- device scratch (no allocs allowed) ----------------
__device__ __nv_bfloat16 g_P_hi[(size_t)NPTS * 1024];
__device__ __nv_bfloat16 g_P_lo[(size_t)NPTS * 1024];
__device__ __nv_bfloat16 g_W3T_hi[COUT * 1024];
__device__ __nv_bfloat16 g_W3T_lo[COUT * 1024];
__device__ int g_start[NPTS + 1];

__device__ __forceinline__ float celu_fast(float x) {
    return x > 0.0f ? x : (__expf(x) - 1.0f);
}
__device__ __forceinline__ uint32_t smem_u32(const void* p) {
    uint32_t a;
    asm("{ .reg .u64 t; cvta.to.shared.u64 t, %1; cvt.u32.u64 %0, t; }" : "=r"(a) : "l"(p));
    return a;
}
__device__ __forceinline__ void cp16(uint32_t dst, const void* src) {
    asm volatile("cp.async.cg.shared.global [%0], [%1], 16;" :: "r"(dst), "l"(src) : "memory");
}
#define CP_COMMIT() asm volatile("cp.async.commit_group;" ::: "memory")
#define CP_WAIT(n)  asm volatile("cp.async.wait_group %0;" :: "n"(n) : "memory")

#define LDMATRIX_X4(r0, r1, r2, r3, addr) \
    asm volatile("ldmatrix.sync.aligned.m8n8.x4.shared.b16 {%0,%1,%2,%3}, [%4];" \
                 : "=r"(r0), "=r"(r1), "=r"(r2), "=r"(r3) : "r"(addr))
#define LDMATRIX_X4_T(r0, r1, r2, r3, addr) \
    asm volatile("ldmatrix.sync.aligned.m8n8.x4.trans.shared.b16 {%0,%1,%2,%3}, [%4];" \
                 : "=r"(r0), "=r"(r1), "=r"(r2), "=r"(r3) : "r"(addr))

#define MMA_BF16(C, A, B0, B1) \
    asm volatile("mma.sync.aligned.m16n8k16.row.col.f32.bf16.bf16.f32 " \
        "{%0,%1,%2,%3}, {%4,%5,%6,%7}, {%8,%9}, {%0,%1,%2,%3};" \
        : "+f"((C)[0]), "+f"((C)[1]), "+f"((C)[2]), "+f"((C)[3]) \
        : "r"((A)[0]), "r"((A)[1]), "r"((A)[2]), "r"((A)[3]), "r"(B0), "r"(B1))

__device__ __forceinline__ uint32_t pack_bf16x2(float lo, float hi) {
    __nv_bfloat162 h2;
    h2.x = __float2bfloat16_rn(lo);
    h2.y = __float2bfloat16_rn(hi);
    return *(uint32_t*)&h2;
}

// ---------------------------------------------------------------------------
// Kernel A: segment offsets
// ---------------------------------------------------------------------------
__global__ void offsets_kernel(const int* __restrict__ oi) {
    int e = blockIdx.x * 256 + threadIdx.x;
    if (e >= NEDGE) return;
    int v = oi[e];
    if (e == 0) {
        for (int n = 0; n <= v; n++) g_start[n] = 0;
    } else {
        int p = oi[e - 1];
        for (int n = p + 1; n <= v; n++) g_start[n] = e;
    }
    if (e == NEDGE - 1) {
        for (int n = v + 1; n <= NPTS; n++) g_start[n] = NEDGE;
    }
}

// ---------------------------------------------------------------------------
// Kernel B: W3 transpose + bf16 hi/lo split
// ---------------------------------------------------------------------------
__global__ void prep_w3_kernel(const float* __restrict__ W3) {
    int t = blockIdx.x * 256 + threadIdx.x;
    int k = t >> 6, n = t & 63;
    float v = W3[t];
    __nv_bfloat16 hi = __float2bfloat16_rn(v);
    __nv_bfloat16 lo = __float2bfloat16_rn(v - __bfloat162float(hi));
    g_W3T_hi[n * 1024 + k] = hi;
    g_W3T_lo[n * 1024 + k] = lo;
}

// ---------------------------------------------------------------------------
// Kernel C: tensor-core edge kernel. Warp per point, 4 warps/CTA.
// Per 16-edge tile: scalar H/X -> GEMM1 (H@W2, celu) -> GEMM2 (X^T @ M).
// All smem warp-private except W1/W2 (CTA-shared, read-only).
// ---------------------------------------------------------------------------
#define HP 48     // pitch of s_h / s_xT rows (bytes)
#define MP 144    // pitch of s_M rows (bytes)

__global__ __launch_bounds__(128) void edge_tc_kernel(
    const float* __restrict__ x_in,
    const float* __restrict__ pos_in,
    const float* __restrict__ pos_out,
    const int*   __restrict__ in_index,
    const float* __restrict__ W1,
    const float* __restrict__ W2)
{
    __shared__ __align__(16) float sW1[48];
    __shared__ __align__(16) char s_w2t[2][64 * HP];      // W2^T split: [n][k=c]
    __shared__ __align__(16) char s_h [4][2][16 * HP];    // H split: [e][c]
    __shared__ __align__(16) char s_xT[4][2][16 * HP];    // X^T split: [c][e]
    __shared__ __align__(16) char s_M [4][2][16 * MP];    // M split: [e][m]

    const int tid  = threadIdx.x;
    const int warp = tid >> 5;
    const int lane = tid & 31;

    if (tid < 48) sW1[tid] = W1[tid];
    for (int i = tid; i < 1024; i += 128) {
        int c = i >> 6, nn = i & 63;
        float v = W2[i];
        __nv_bfloat16 hi = __float2bfloat16_rn(v);
        __nv_bfloat16 lo = __float2bfloat16_rn(v - __bfloat162float(hi));
        *(__nv_bfloat16*)&s_w2t[0][nn * HP + c * 2] = hi;
        *(__nv_bfloat16*)&s_w2t[1][nn * HP + c * 2] = lo;
    }
    __syncthreads();

    // hoist W2^T B-fragments (loop-invariant): 4 ldmatrix.x4 per half
    uint32_t bW2h[4][4], bW2l[4][4];
    {
        uint32_t rsel = (uint32_t)((lane & 7) + ((lane & 16) ? 8 : 0));
        uint32_t csel = (lane & 8) ? 16u : 0u;
        uint32_t b0h = smem_u32(s_w2t[0]);
        uint32_t b0l = smem_u32(s_w2t[1]);
#pragma unroll
        for (int j = 0; j < 4; j++) {
            uint32_t a = (rsel + j * 16) * HP + csel;
            LDMATRIX_X4(bW2h[j][0], bW2h[j][1], bW2h[j][2], bW2h[j][3], b0h + a);
            LDMATRIX_X4(bW2l[j][0], bW2l[j][1], bW2l[j][2], bW2l[j][3], b0l + a);
        }
    }

    const int n = blockIdx.x * 4 + warp;
    const int start = g_start[n];
    const int cnt   = g_start[n + 1] - start;
    const int nl    = cnt < KMAX ? cnt : KMAX;
    const float inv = (cnt > 0) ? (1.0f / (float)cnt) : 0.0f;

    const float po0 = __ldg(pos_out + 3 * n + 0);
    const float po1 = __ldg(pos_out + 3 * n + 1);
    const float po2 = __ldg(pos_out + 3 * n + 2);

    float P[32];
#pragma unroll
    for (int i = 0; i < 32; i++) P[i] = 0.0f;

    const uint32_t shH  = smem_u32(s_h[warp][0]);
    const uint32_t shL  = smem_u32(s_h[warp][1]);
    const uint32_t sxH  = smem_u32(s_xT[warp][0]);
    const uint32_t sxL  = smem_u32(s_xT[warp][1]);
    const uint32_t smH  = smem_u32(s_M[warp][0]);
    const uint32_t smL  = smem_u32(s_M[warp][1]);

    // ldmatrix address components
    const uint32_t aOff  = (uint32_t)(lane & 15) * HP + ((lane >> 4) & 1) * 16;  // A pattern
    const uint32_t tRow  = (uint32_t)((lane & 7) + (((lane >> 3) & 1) << 3));    // trans-B pattern
    const uint32_t tCol  = ((lane >> 4) & 1) * 16;
    const int g  = lane >> 2;
    const int q  = lane & 3;

    const int tiles = (nl + 15) >> 4;
    for (int t = 0; t < tiles; t++) {
        // ---- scalar prologue: 2 lanes per edge, 8 channels each ----
        {
            const int e  = lane >> 1;
            const int rr = (lane & 1) * 8;
            const int er = t * 16 + e;
            float h[8], x[8];
            if (er < nl) {
                int idx  = __ldg(in_index + start + er);
                float d0 = __ldg(pos_in + 3 * idx + 0) - po0;
                float d1 = __ldg(pos_in + 3 * idx + 1) - po1;
                float d2 = __ldg(pos_in + 3 * idx + 2) - po2;
#pragma unroll
                for (int j = 0; j < 8; j++) {
                    int c = rr + j;
                    float a = fmaf(d0, sW1[c], fmaf(d1, sW1[16 + c], d2 * sW1[32 + c]));
                    h[j] = celu_fast(a);
                }
                const float4* xr = (const float4*)(x_in + (size_t)idx * CIN + rr);
                float4 v0 = __ldg(xr), v1 = __ldg(xr + 1);
                x[0] = v0.x * inv; x[1] = v0.y * inv; x[2] = v0.z * inv; x[3] = v0.w * inv;
                x[4] = v1.x * inv; x[5] = v1.y * inv; x[6] = v1.z * inv; x[7] = v1.w * inv;
            } else {
#pragma unroll
                for (int j = 0; j < 8; j++) { h[j] = 0.0f; x[j] = 0.0f; }
            }
            // store H split (pairs)
#pragma unroll
            for (int j = 0; j < 4; j++) {
                float v0 = h[2 * j], v1 = h[2 * j + 1];
                __nv_bfloat16 h0 = __float2bfloat16_rn(v0);
                __nv_bfloat16 h1 = __float2bfloat16_rn(v1);
                float l0 = v0 - __bfloat162float(h0);
                float l1 = v1 - __bfloat162float(h1);
                uint32_t off = (uint32_t)e * HP + (rr + 2 * j) * 2;
                __nv_bfloat162 ph; ph.x = h0; ph.y = h1;
                *(uint32_t*)(s_h[warp][0] + off) = *(uint32_t*)&ph;
                *(uint32_t*)(s_h[warp][1] + off) = pack_bf16x2(l0, l1);
            }
            // store X^T split (scattered columns)
#pragma unroll
            for (int j = 0; j < 8; j++) {
                float v = x[j];
                __nv_bfloat16 hi = __float2bfloat16_rn(v);
                __nv_bfloat16 lo = __float2bfloat16_rn(v - __bfloat162float(hi));
                uint32_t off = (uint32_t)(rr + j) * HP + e * 2;
                *(__nv_bfloat16*)(s_xT[warp][0] + off) = hi;
                *(__nv_bfloat16*)(s_xT[warp][1] + off) = lo;
            }
        }
        __syncwarp();

        // ---- GEMM1: M = celu(H @ W2), split to s_M ----
        {
            uint32_t ah[4], al[4];
            LDMATRIX_X4(ah[0], ah[1], ah[2], ah[3], shH + aOff);
            LDMATRIX_X4(al[0], al[1], al[2], al[3], shL + aOff);
#pragma unroll
            for (int j = 0; j < 4; j++) {
#pragma unroll
                for (int sub = 0; sub < 2; sub++) {
                    const int nt = 2 * j + sub;
                    float C1[4] = {0.f, 0.f, 0.f, 0.f};
                    MMA_BF16(C1, ah, bW2h[j][2 * sub], bW2h[j][2 * sub + 1]);
                    MMA_BF16(C1, al, bW2h[j][2 * sub], bW2h[j][2 * sub + 1]);
                    MMA_BF16(C1, ah, bW2l[j][2 * sub], bW2l[j][2 * sub + 1]);
#pragma unroll
                    for (int i = 0; i < 4; i++) C1[i] = celu_fast(C1[i]);
                    // rows g (c0,c1) and g+8 (c2,c3); cols nt*8+2q, +1
                    const uint32_t cb = (uint32_t)(nt * 16 + q * 4);
#pragma unroll
                    for (int r2 = 0; r2 < 2; r2++) {
                        float v0 = C1[2 * r2], v1 = C1[2 * r2 + 1];
                        __nv_bfloat16 h0 = __float2bfloat16_rn(v0);
                        __nv_bfloat16 h1 = __float2bfloat16_rn(v1);
                        float l0 = v0 - __bfloat162float(h0);
                        float l1 = v1 - __bfloat162float(h1);
                        uint32_t off = (uint32_t)(g + 8 * r2) * MP + cb;
                        __nv_bfloat162 ph; ph.x = h0; ph.y = h1;
                        *(uint32_t*)(s_M[warp][0] + off) = *(uint32_t*)&ph;
                        *(uint32_t*)(s_M[warp][1] + off) = pack_bf16x2(l0, l1);
                    }
                }
            }
        }
        __syncwarp();

        // ---- GEMM2: P += X^T @ M ----
        {
            uint32_t axh[4], axl[4];
            LDMATRIX_X4(axh[0], axh[1], axh[2], axh[3], sxH + aOff);
            LDMATRIX_X4(axl[0], axl[1], axl[2], axl[3], sxL + aOff);
#pragma unroll
            for (int pp = 0; pp < 4; pp++) {
                uint32_t bh[4], bl[4];
                uint32_t a = tRow * MP + pp * 32 + tCol;
                LDMATRIX_X4_T(bh[0], bh[1], bh[2], bh[3], smH + a);
                LDMATRIX_X4_T(bl[0], bl[1], bl[2], bl[3], smL + a);
                float* C0 = P + (2 * pp) * 4;
                float* C1 = P + (2 * pp + 1) * 4;
                MMA_BF16(C0, axh, bh[0], bh[1]);
                MMA_BF16(C0, axl, bh[0], bh[1]);
                MMA_BF16(C0, axh, bl[0], bl[1]);
                MMA_BF16(C1, axh, bh[2], bh[3]);
                MMA_BF16(C1, axl, bh[2], bh[3]);
                MMA_BF16(C1, axh, bl[2], bl[3]);
            }
        }
        __syncwarp();
    }

    // ---- store P split to gmem: P[c][m] at n*1024 + c*64 + m ----
    __nv_bfloat16* dh = g_P_hi + (size_t)n * 1024;
    __nv_bfloat16* dl = g_P_lo + (size_t)n * 1024;
#pragma unroll
    for (int nt = 0; nt < 8; nt++) {
#pragma unroll
        for (int r2 = 0; r2 < 2; r2++) {
            float v0 = P[nt * 4 + 2 * r2], v1 = P[nt * 4 + 2 * r2 + 1];
            __nv_bfloat16 h0 = __float2bfloat16_rn(v0);
            __nv_bfloat16 h1 = __float2bfloat16_rn(v1);
            float l0 = v0 - __bfloat162float(h0);
            float l1 = v1 - __bfloat162float(h1);
            int c = g + 8 * r2;
            int m = nt * 8 + 2 * q;
            __nv_bfloat162 ph; ph.x = h0; ph.y = h1;
            *(uint32_t*)(dh + c * 64 + m) = *(uint32_t*)&ph;
            *(uint32_t*)(dl + c * 64 + m) = pack_bf16x2(l0, l1);
        }
    }
}

// ---------------------------------------------------------------------------
// Kernel D: out = P @ W3 + b3. M=64/CTA, 128 thr (4 warps x m16), 4 stages.
// ---------------------------------------------------------------------------
#define PITCH_B 80
#define OFF_AHI 0
#define OFF_ALO 5120
#define OFF_BHI 10240
#define OFF_BLO 15360
#define STAGE_BYTES 20480
#define GEMM_SMEM (4 * STAGE_BYTES)

__global__ __launch_bounds__(128) void gemm_mma(
    const float* __restrict__ b3,
    float* __restrict__ out)
{
    extern __shared__ char dsm[];
    const uint32_t sbase = smem_u32(dsm);

    const int tid  = threadIdx.x;
    const int warp = tid >> 5;
    const int lane = tid & 31;
    const int ctaM = blockIdx.x * 64;

    const char* Ahi_g = (const char*)(g_P_hi + (size_t)ctaM * 1024);
    const char* Alo_g = (const char*)(g_P_lo + (size_t)ctaM * 1024);
    const char* Bhi_g = (const char*)g_W3T_hi;
    const char* Blo_g = (const char*)g_W3T_lo;

    auto issue_loads = [&](int kt, int s) {
        uint32_t base = sbase + s * STAGE_BYTES;
        const int kb = kt * 64;
#pragma unroll
        for (int i = 0; i < 2; i++) {
            int idx = tid + i * 128;
            int row = idx >> 2, seg = idx & 3;
            uint32_t d = base + row * PITCH_B + seg * 16;
            size_t gofs = (size_t)row * 2048 + kb + seg * 16;
            cp16(d + OFF_AHI, Ahi_g + gofs);
            cp16(d + OFF_ALO, Alo_g + gofs);
            cp16(d + OFF_BHI, Bhi_g + gofs);
            cp16(d + OFF_BLO, Blo_g + gofs);
        }
    };

    float C[8][4];
#pragma unroll
    for (int nt = 0; nt < 8; nt++)
#pragma unroll
        for (int i = 0; i < 4; i++) C[nt][i] = 0.0f;

    const uint32_t aRow  = warp * 16 + (lane & 15);
    const uint32_t aColB = ((lane >> 4) & 1) * 16;
    const uint32_t bRow  = (lane & 7) + ((lane & 16) ? 8 : 0);
    const uint32_t bColB = (lane & 8) ? 16 : 0;

    issue_loads(0, 0); CP_COMMIT();
    issue_loads(1, 1); CP_COMMIT();
    issue_loads(2, 2); CP_COMMIT();

    for (int kt = 0; kt < 32; kt++) {
        CP_WAIT(2);
        __syncthreads();
        if (kt + 3 < 32) issue_loads(kt + 3, (kt + 3) & 3);
        CP_COMMIT();

        const uint32_t base = sbase + (kt & 3) * STAGE_BYTES;
#pragma unroll
        for (int ks = 0; ks < 2; ks++) {
            const uint32_t kOffB = ks * 32;
            uint32_t ah[4], al[4];
            uint32_t aa = base + aRow * PITCH_B + kOffB + aColB;
            LDMATRIX_X4(ah[0], ah[1], ah[2], ah[3], aa + OFF_AHI);
            LDMATRIX_X4(al[0], al[1], al[2], al[3], aa + OFF_ALO);
#pragma unroll
            for (int p = 0; p < 4; p++) {
                uint32_t bh0, bh1, bh2, bh3, bl0, bl1, bl2, bl3;
                uint32_t ba = base + (p * 16 + bRow) * PITCH_B + kOffB + bColB;
                LDMATRIX_X4(bh0, bh1, bh2, bh3, ba + OFF_BHI);
                LDMATRIX_X4(bl0, bl1, bl2, bl3, ba + OFF_BLO);
                MMA_BF16(C[2 * p],     ah, bh0, bh1);
                MMA_BF16(C[2 * p],     al, bh0, bh1);
                MMA_BF16(C[2 * p],     ah, bl0, bl1);
                MMA_BF16(C[2 * p + 1], ah, bh2, bh3);
                MMA_BF16(C[2 * p + 1], al, bh2, bh3);
                MMA_BF16(C[2 * p + 1], ah, bl2, bl3);
            }
        }
    }

    const int g  = lane >> 2;
    const int q2 = (lane & 3) * 2;
    const int rowBase = ctaM + warp * 16;
#pragma unroll
    for (int nt = 0; nt < 8; nt++) {
        const int col = nt * 8 + q2;
        float2 bb = *(const float2*)(b3 + col);
        float2 v0, v1;
        v0.x = C[nt][0] + bb.x;
        v0.y = C[nt][1] + bb.y;
        v1.x = C[nt][2] + bb.x;
        v1.y = C[nt][3] + bb.y;
        *(float2*)(out + (size_t)(rowBase + g) * COUT + col) = v0;
        *(float2*)(out + (size_t)(rowBase + g + 8) * COUT + col) = v1;
    }
}

// ---------------------------------------------------------------------------
extern "C" void kernel_launch(void* const* d_in, const int* in_sizes, int n_in,
                              void* d_out, int out_size) {
    const float* x_in      = (const float*)d_in[0];
    const float* pos_in    = (const float*)d_in[1];
    const float* pos_out   = (const float*)d_in[2];
    const int*   in_index  = (const int*)d_in[3];
    const int*   out_index = (const int*)d_in[4];
    const float* W1        = (const float*)d_in[5];
    const float* W2        = (const float*)d_in[6];
    const float* W3        = (const float*)d_in[7];
    const float* b3        = (const float*)d_in[8];
    float* out = (float*)d_out;

    cudaFuncSetAttribute(gemm_mma, cudaFuncAttributeMaxDynamicSharedMemorySize, GEMM_SMEM);

    offsets_kernel<<<(NEDGE + 255) / 256, 256>>>(out_index);
    prep_w3_kernel<<<(1024 * 64) / 256, 256>>>(W3);
    edge_tc_kernel<<<NPTS / 4, 128>>>(x_in, pos_in, pos_out, in_index, W1, W2);
    gemm_mma<<<NPTS / 64, 128, GEMM_SMEM>>>(b3, out);
}

// round 5
// speedup vs baseline: 2.1071x; 1.2095x over previous
#include <cuda_runtime.h>
#include <cuda_bf16.h>
#include <cuda_fp16.h>
#include <math.h>
#include <stdint.h>

#define NPTS  32768
#define NEDGE 786432
#define CIN   16
#define CMID  64
#define COUT  64
#define KMAX  64

// ---------------- device scratch ----------------
__device__ __nv_bfloat16 g_P_hi[(size_t)NPTS * 1024];
__device__ __nv_bfloat16 g_P_lo[(size_t)NPTS * 1024];
__device__ __nv_bfloat16 g_W3T_hi[COUT * 1024];
__device__ __nv_bfloat16 g_W3T_lo[COUT * 1024];
__device__ int g_start[NPTS + 1];

__device__ __forceinline__ float celu_fast(float x) {
    return x > 0.0f ? x : (__expf(x) - 1.0f);
}
__device__ __forceinline__ uint32_t smem_u32(const void* p) {
    uint32_t a;
    asm("{ .reg .u64 t; cvta.to.shared.u64 t, %1; cvt.u32.u64 %0, t; }" : "=r"(a) : "l"(p));
    return a;
}
__device__ __forceinline__ void cp16(uint32_t dst, const void* src) {
    asm volatile("cp.async.cg.shared.global [%0], [%1], 16;" :: "r"(dst), "l"(src) : "memory");
}
#define CP_COMMIT() asm volatile("cp.async.commit_group;" ::: "memory")
#define CP_WAIT(n)  asm volatile("cp.async.wait_group %0;" :: "n"(n) : "memory")

#define LDMATRIX_X4(r0, r1, r2, r3, addr) \
    asm volatile("ldmatrix.sync.aligned.m8n8.x4.shared.b16 {%0,%1,%2,%3}, [%4];" \
                 : "=r"(r0), "=r"(r1), "=r"(r2), "=r"(r3) : "r"(addr))
#define LDMATRIX_X4_T(r0, r1, r2, r3, addr) \
    asm volatile("ldmatrix.sync.aligned.m8n8.x4.trans.shared.b16 {%0,%1,%2,%3}, [%4];" \
                 : "=r"(r0), "=r"(r1), "=r"(r2), "=r"(r3) : "r"(addr))

#define MMA_BF16(C, A, B0, B1) \
    asm volatile("mma.sync.aligned.m16n8k16.row.col.f32.bf16.bf16.f32 " \
        "{%0,%1,%2,%3}, {%4,%5,%6,%7}, {%8,%9}, {%0,%1,%2,%3};" \
        : "+f"((C)[0]), "+f"((C)[1]), "+f"((C)[2]), "+f"((C)[3]) \
        : "r"((A)[0]), "r"((A)[1]), "r"((A)[2]), "r"((A)[3]), "r"(B0), "r"(B1))

#define MMA_FP16(C, A, B0, B1) \
    asm volatile("mma.sync.aligned.m16n8k16.row.col.f32.f16.f16.f32 " \
        "{%0,%1,%2,%3}, {%4,%5,%6,%7}, {%8,%9}, {%0,%1,%2,%3};" \
        : "+f"((C)[0]), "+f"((C)[1]), "+f"((C)[2]), "+f"((C)[3]) \
        : "r"((A)[0]), "r"((A)[1]), "r"((A)[2]), "r"((A)[3]), "r"(B0), "r"(B1))

__device__ __forceinline__ uint32_t pack_bf16x2(float lo, float hi) {
    __nv_bfloat162 h2;
    h2.x = __float2bfloat16_rn(lo);
    h2.y = __float2bfloat16_rn(hi);
    return *(uint32_t*)&h2;
}
__device__ __forceinline__ uint32_t pack_half2(float a, float b) {
    __half2 h = __floats2half2_rn(a, b);
    return *(uint32_t*)&h;
}

// ---------------------------------------------------------------------------
// Kernel A: segment offsets
// ---------------------------------------------------------------------------
__global__ void offsets_kernel(const int* __restrict__ oi) {
    int e = blockIdx.x * 256 + threadIdx.x;
    if (e >= NEDGE) return;
    int v = oi[e];
    if (e == 0) {
        for (int n = 0; n <= v; n++) g_start[n] = 0;
    } else {
        int p = oi[e - 1];
        for (int n = p + 1; n <= v; n++) g_start[n] = e;
    }
    if (e == NEDGE - 1) {
        for (int n = v + 1; n <= NPTS; n++) g_start[n] = NEDGE;
    }
}

// ---------------------------------------------------------------------------
// Kernel B: W3 transpose + bf16 hi/lo split
// ---------------------------------------------------------------------------
__global__ void prep_w3_kernel(const float* __restrict__ W3) {
    int t = blockIdx.x * 256 + threadIdx.x;
    int k = t >> 6, n = t & 63;
    float v = W3[t];
    __nv_bfloat16 hi = __float2bfloat16_rn(v);
    __nv_bfloat16 lo = __float2bfloat16_rn(v - __bfloat162float(hi));
    g_W3T_hi[n * 1024 + k] = hi;
    g_W3T_lo[n * 1024 + k] = lo;
}

// ---------------------------------------------------------------------------
// Kernel C: tensor-core edge kernel, fp16 single precision, batched prologue.
// Warp per point, 4 warps/CTA.
// ---------------------------------------------------------------------------
#define PHP 48     // s_h pitch: [e][c], 32B data + 16 pad
#define PXP 144    // s_xT pitch: [c][e], 128B data + 16 pad
#define PMP 144    // s_M pitch: [e][m], 128B data + 16 pad
#define WHP 48     // s_w2t pitch

__global__ __launch_bounds__(128) void edge_tc_kernel(
    const float* __restrict__ x_in,
    const float* __restrict__ pos_in,
    const float* __restrict__ pos_out,
    const int*   __restrict__ in_index,
    const float* __restrict__ W1,
    const float* __restrict__ W2)
{
    __shared__ __align__(16) float sW1[48];
    __shared__ __align__(16) char s_w2t[64 * WHP];     // W2^T fp16: [n][c]
    __shared__ __align__(16) char s_h [4][64 * PHP];   // H fp16: [e][c]
    __shared__ __align__(16) char s_xT[4][16 * PXP];   // X^T fp16: [c][e]
    __shared__ __align__(16) char s_M [4][16 * PMP];   // M fp16: [e][m] per tile

    const int tid  = threadIdx.x;
    const int warp = tid >> 5;
    const int lane = tid & 31;

    if (tid < 48) sW1[tid] = W1[tid];
    for (int i = tid; i < 1024; i += 128) {
        int c = i >> 6, nn = i & 63;
        *(__half*)&s_w2t[nn * WHP + c * 2] = __float2half_rn(W2[i]);
    }
    __syncthreads();

    // hoist W2^T B-fragments
    uint32_t bW2[4][4];
    {
        uint32_t rsel = (uint32_t)((lane & 7) + ((lane & 16) ? 8 : 0));
        uint32_t csel = (lane & 8) ? 16u : 0u;
        uint32_t b0 = smem_u32(s_w2t);
#pragma unroll
        for (int j = 0; j < 4; j++) {
            uint32_t a = (rsel + j * 16) * WHP + csel;
            LDMATRIX_X4(bW2[j][0], bW2[j][1], bW2[j][2], bW2[j][3], b0 + a);
        }
    }

    const int n = blockIdx.x * 4 + warp;
    const int start = g_start[n];
    const int cnt   = g_start[n + 1] - start;
    const int nl    = cnt < KMAX ? cnt : KMAX;
    const float inv = (cnt > 0) ? (1.0f / (float)cnt) : 0.0f;
    const int tiles = (nl + 15) >> 4;
    const int epad  = tiles * 16;

    const float po0 = __ldg(pos_out + 3 * n + 0);
    const float po1 = __ldg(pos_out + 3 * n + 1);
    const float po2 = __ldg(pos_out + 3 * n + 2);

    float P[32];
#pragma unroll
    for (int i = 0; i < 32; i++) P[i] = 0.0f;

    const uint32_t shB = smem_u32(s_h[warp]);
    const uint32_t sxB = smem_u32(s_xT[warp]);
    const uint32_t smB = smem_u32(s_M[warp]);

    // ---- batched scalar prologue: all edges, 2 lanes/edge x 8 channels ----
    {
        const int rr = (lane & 1) * 8;
        for (int e = (lane >> 1); e < epad; e += 16) {
            float h[8], x[8];
            if (e < nl) {
                int idx  = __ldg(in_index + start + e);
                float d0 = __ldg(pos_in + 3 * idx + 0) - po0;
                float d1 = __ldg(pos_in + 3 * idx + 1) - po1;
                float d2 = __ldg(pos_in + 3 * idx + 2) - po2;
#pragma unroll
                for (int j = 0; j < 8; j++) {
                    int c = rr + j;
                    float a = fmaf(d0, sW1[c], fmaf(d1, sW1[16 + c], d2 * sW1[32 + c]));
                    h[j] = celu_fast(a);
                }
                const float4* xr = (const float4*)(x_in + (size_t)idx * CIN + rr);
                float4 v0 = __ldg(xr), v1 = __ldg(xr + 1);
                x[0] = v0.x * inv; x[1] = v0.y * inv; x[2] = v0.z * inv; x[3] = v0.w * inv;
                x[4] = v1.x * inv; x[5] = v1.y * inv; x[6] = v1.z * inv; x[7] = v1.w * inv;
            } else {
#pragma unroll
                for (int j = 0; j < 8; j++) { h[j] = 0.0f; x[j] = 0.0f; }
            }
#pragma unroll
            for (int j = 0; j < 4; j++) {
                *(uint32_t*)(s_h[warp] + (uint32_t)e * PHP + (rr + 2 * j) * 2) =
                    pack_half2(h[2 * j], h[2 * j + 1]);
            }
#pragma unroll
            for (int j = 0; j < 8; j++) {
                *(__half*)(s_xT[warp] + (uint32_t)(rr + j) * PXP + e * 2) =
                    __float2half_rn(x[j]);
            }
        }
    }
    __syncwarp();

    // ldmatrix address components
    const uint32_t aRowOff = (uint32_t)(lane & 15);
    const uint32_t aColB   = ((lane >> 4) & 1) * 16;
    const uint32_t tRow    = (uint32_t)((lane & 7) + (((lane >> 3) & 1) << 3));
    const uint32_t tCol    = ((lane >> 4) & 1) * 16;
    const int g = lane >> 2;
    const int q = lane & 3;

    for (int t = 0; t < tiles; t++) {
        // ---- GEMM1: M = celu(H @ W2) ----
        {
            uint32_t a[4];
            LDMATRIX_X4(a[0], a[1], a[2], a[3],
                        shB + (t * 16 + aRowOff) * PHP + aColB);
#pragma unroll
            for (int j = 0; j < 4; j++) {
#pragma unroll
                for (int sub = 0; sub < 2; sub++) {
                    const int nt = 2 * j + sub;
                    float C1[4] = {0.f, 0.f, 0.f, 0.f};
                    MMA_FP16(C1, a, bW2[j][2 * sub], bW2[j][2 * sub + 1]);
                    const uint32_t cb = (uint32_t)(nt * 16 + q * 4);
#pragma unroll
                    for (int r2 = 0; r2 < 2; r2++) {
                        float v0 = celu_fast(C1[2 * r2]);
                        float v1 = celu_fast(C1[2 * r2 + 1]);
                        *(uint32_t*)(s_M[warp] + (uint32_t)(g + 8 * r2) * PMP + cb) =
                            pack_half2(v0, v1);
                    }
                }
            }
        }
        __syncwarp();

        // ---- GEMM2: P += X^T @ M ----
        {
            uint32_t ax[4];
            LDMATRIX_X4(ax[0], ax[1], ax[2], ax[3],
                        sxB + aRowOff * PXP + t * 32 + aColB);
#pragma unroll
            for (int pp = 0; pp < 4; pp++) {
                uint32_t b0, b1, b2, b3;
                LDMATRIX_X4_T(b0, b1, b2, b3, smB + tRow * PMP + pp * 32 + tCol);
                MMA_FP16(P + (2 * pp) * 4,     ax, b0, b1);
                MMA_FP16(P + (2 * pp + 1) * 4, ax, b2, b3);
            }
        }
        __syncwarp();
    }

    // ---- store P split (bf16 hi/lo) to gmem ----
    __nv_bfloat16* dh = g_P_hi + (size_t)n * 1024;
    __nv_bfloat16* dl = g_P_lo + (size_t)n * 1024;
#pragma unroll
    for (int nt = 0; nt < 8; nt++) {
#pragma unroll
        for (int r2 = 0; r2 < 2; r2++) {
            float v0 = P[nt * 4 + 2 * r2], v1 = P[nt * 4 + 2 * r2 + 1];
            __nv_bfloat16 h0 = __float2bfloat16_rn(v0);
            __nv_bfloat16 h1 = __float2bfloat16_rn(v1);
            float l0 = v0 - __bfloat162float(h0);
            float l1 = v1 - __bfloat162float(h1);
            int c = g + 8 * r2;
            int m = nt * 8 + 2 * q;
            __nv_bfloat162 ph; ph.x = h0; ph.y = h1;
            *(uint32_t*)(dh + c * 64 + m) = *(uint32_t*)&ph;
            *(uint32_t*)(dl + c * 64 + m) = pack_bf16x2(l0, l1);
        }
    }
}

// ---------------------------------------------------------------------------
// Kernel D: out = P @ W3 + b3. M=128/CTA, 256 thr (8 warps x m16n64), 4-stage.
// ---------------------------------------------------------------------------
#define PITCH_B 80
#define OFF_AHI 0
#define OFF_ALO 10240
#define OFF_BHI 20480
#define OFF_BLO 25600
#define STAGE_BYTES 30720
#define GEMM_SMEM (4 * STAGE_BYTES)

__global__ __launch_bounds__(256) void gemm_mma(
    const float* __restrict__ b3,
    float* __restrict__ out)
{
    extern __shared__ char dsm[];
    const uint32_t sbase = smem_u32(dsm);

    const int tid  = threadIdx.x;
    const int warp = tid >> 5;
    const int lane = tid & 31;
    const int ctaM = blockIdx.x * 128;

    const char* Ahi_g = (const char*)(g_P_hi + (size_t)ctaM * 1024);
    const char* Alo_g = (const char*)(g_P_lo + (size_t)ctaM * 1024);
    const char* Bhi_g = (const char*)g_W3T_hi;
    const char* Blo_g = (const char*)g_W3T_lo;

    auto issue_loads = [&](int kt, int s) {
        uint32_t base = sbase + s * STAGE_BYTES;
        const int kb = kt * 64;
#pragma unroll
        for (int i = 0; i < 2; i++) {
            int idx = tid + i * 256;        // 0..511 -> A rows
            int row = idx >> 2, seg = idx & 3;
            uint32_t d = base + row * PITCH_B + seg * 16;
            size_t gofs = (size_t)row * 2048 + kb + seg * 16;
            cp16(d + OFF_AHI, Ahi_g + gofs);
            cp16(d + OFF_ALO, Alo_g + gofs);
        }
        {
            int row = tid >> 2, seg = tid & 3;  // 0..63 B rows
            uint32_t d = base + row * PITCH_B + seg * 16;
            size_t gofs = (size_t)row * 2048 + kb + seg * 16;
            cp16(d + OFF_BHI, Bhi_g + gofs);
            cp16(d + OFF_BLO, Blo_g + gofs);
        }
    };

    float C[8][4];
#pragma unroll
    for (int nt = 0; nt < 8; nt++)
#pragma unroll
        for (int i = 0; i < 4; i++) C[nt][i] = 0.0f;

    const uint32_t aRow  = warp * 16 + (lane & 15);
    const uint32_t aColB = ((lane >> 4) & 1) * 16;
    const uint32_t bRow  = (lane & 7) + ((lane & 16) ? 8 : 0);
    const uint32_t bColB = (lane & 8) ? 16 : 0;

    issue_loads(0, 0); CP_COMMIT();
    issue_loads(1, 1); CP_COMMIT();
    issue_loads(2, 2); CP_COMMIT();

    for (int kt = 0; kt < 32; kt++) {
        CP_WAIT(2);
        __syncthreads();
        if (kt + 3 < 32) issue_loads(kt + 3, (kt + 3) & 3);
        CP_COMMIT();

        const uint32_t base = sbase + (kt & 3) * STAGE_BYTES;
#pragma unroll
        for (int ks = 0; ks < 2; ks++) {
            const uint32_t kOffB = ks * 32;
            uint32_t ah[4], al[4];
            uint32_t aa = base + aRow * PITCH_B + kOffB + aColB;
            LDMATRIX_X4(ah[0], ah[1], ah[2], ah[3], aa + OFF_AHI);
            LDMATRIX_X4(al[0], al[1], al[2], al[3], aa + OFF_ALO);
#pragma unroll
            for (int p = 0; p < 4; p++) {
                uint32_t bh0, bh1, bh2, bh3, bl0, bl1, bl2, bl3;
                uint32_t ba = base + (p * 16 + bRow) * PITCH_B + kOffB + bColB;
                LDMATRIX_X4(bh0, bh1, bh2, bh3, ba + OFF_BHI);
                LDMATRIX_X4(bl0, bl1, bl2, bl3, ba + OFF_BLO);
                MMA_BF16(C[2 * p],     ah, bh0, bh1);
                MMA_BF16(C[2 * p],     al, bh0, bh1);
                MMA_BF16(C[2 * p],     ah, bl0, bl1);
                MMA_BF16(C[2 * p + 1], ah, bh2, bh3);
                MMA_BF16(C[2 * p + 1], al, bh2, bh3);
                MMA_BF16(C[2 * p + 1], ah, bl2, bl3);
            }
        }
    }

    const int g  = lane >> 2;
    const int q2 = (lane & 3) * 2;
    const int rowBase = ctaM + warp * 16;
#pragma unroll
    for (int nt = 0; nt < 8; nt++) {
        const int col = nt * 8 + q2;
        float2 bb = *(const float2*)(b3 + col);
        float2 v0, v1;
        v0.x = C[nt][0] + bb.x;
        v0.y = C[nt][1] + bb.y;
        v1.x = C[nt][2] + bb.x;
        v1.y = C[nt][3] + bb.y;
        *(float2*)(out + (size_t)(rowBase + g) * COUT + col) = v0;
        *(float2*)(out + (size_t)(rowBase + g + 8) * COUT + col) = v1;
    }
}

// ---------------------------------------------------------------------------
extern "C" void kernel_launch(void* const* d_in, const int* in_sizes, int n_in,
                              void* d_out, int out_size) {
    const float* x_in      = (const float*)d_in[0];
    const float* pos_in    = (const float*)d_in[1];
    const float* pos_out   = (const float*)d_in[2];
    const int*   in_index  = (const int*)d_in[3];
    const int*   out_index = (const int*)d_in[4];
    const float* W1        = (const float*)d_in[5];
    const float* W2        = (const float*)d_in[6];
    const float* W3        = (const float*)d_in[7];
    const float* b3        = (const float*)d_in[8];
    float* out = (float*)d_out;

    cudaFuncSetAttribute(gemm_mma, cudaFuncAttributeMaxDynamicSharedMemorySize, GEMM_SMEM);

    offsets_kernel<<<(NEDGE + 255) / 256, 256>>>(out_index);
    prep_w3_kernel<<<(1024 * 64) / 256, 256>>>(W3);
    edge_tc_kernel<<<NPTS / 4, 128>>>(x_in, pos_in, pos_out, in_index, W1, W2);
    gemm_mma<<<NPTS / 128, 256, GEMM_SMEM>>>(b3, out);
}

// round 6
// speedup vs baseline: 2.2163x; 1.0518x over previous
#include <cuda_runtime.h>
#include <cuda_bf16.h>
#include <cuda_fp16.h>
#include <math.h>
#include <stdint.h>

#define NPTS  32768
#define NEDGE 786432
#define CIN   16
#define CMID  64
#define COUT  64
#define KMAX  64

// ---------------- device scratch ----------------
__device__ __nv_bfloat16 g_P_hi[(size_t)NPTS * 1024];
__device__ __nv_bfloat16 g_P_lo[(size_t)NPTS * 1024];
__device__ __nv_bfloat16 g_W3T_hi[COUT * 1024];
__device__ __nv_bfloat16 g_W3T_lo[COUT * 1024];
__device__ int g_start[NPTS + 1];

__device__ __forceinline__ float celu_fast(float x) {
    return x > 0.0f ? x : (__expf(x) - 1.0f);
}
__device__ __forceinline__ uint32_t smem_u32(const void* p) {
    uint32_t a;
    asm("{ .reg .u64 t; cvta.to.shared.u64 t, %1; cvt.u32.u64 %0, t; }" : "=r"(a) : "l"(p));
    return a;
}
__device__ __forceinline__ void cp16(uint32_t dst, const void* src) {
    asm volatile("cp.async.cg.shared.global [%0], [%1], 16;" :: "r"(dst), "l"(src) : "memory");
}
#define CP_COMMIT() asm volatile("cp.async.commit_group;" ::: "memory")
#define CP_WAIT(n)  asm volatile("cp.async.wait_group %0;" :: "n"(n) : "memory")

#define LDMATRIX_X4(r0, r1, r2, r3, addr) \
    asm volatile("ldmatrix.sync.aligned.m8n8.x4.shared.b16 {%0,%1,%2,%3}, [%4];" \
                 : "=r"(r0), "=r"(r1), "=r"(r2), "=r"(r3) : "r"(addr))
#define LDMATRIX_X4_T(r0, r1, r2, r3, addr) \
    asm volatile("ldmatrix.sync.aligned.m8n8.x4.trans.shared.b16 {%0,%1,%2,%3}, [%4];" \
                 : "=r"(r0), "=r"(r1), "=r"(r2), "=r"(r3) : "r"(addr))

#define MMA_BF16(C, A, B0, B1) \
    asm volatile("mma.sync.aligned.m16n8k16.row.col.f32.bf16.bf16.f32 " \
        "{%0,%1,%2,%3}, {%4,%5,%6,%7}, {%8,%9}, {%0,%1,%2,%3};" \
        : "+f"((C)[0]), "+f"((C)[1]), "+f"((C)[2]), "+f"((C)[3]) \
        : "r"((A)[0]), "r"((A)[1]), "r"((A)[2]), "r"((A)[3]), "r"(B0), "r"(B1))

#define MMA_FP16(C, A, B0, B1) \
    asm volatile("mma.sync.aligned.m16n8k16.row.col.f32.f16.f16.f32 " \
        "{%0,%1,%2,%3}, {%4,%5,%6,%7}, {%8,%9}, {%0,%1,%2,%3};" \
        : "+f"((C)[0]), "+f"((C)[1]), "+f"((C)[2]), "+f"((C)[3]) \
        : "r"((A)[0]), "r"((A)[1]), "r"((A)[2]), "r"((A)[3]), "r"(B0), "r"(B1))

__device__ __forceinline__ uint32_t pack_bf16x2(float lo, float hi) {
    __nv_bfloat162 h2;
    h2.x = __float2bfloat16_rn(lo);
    h2.y = __float2bfloat16_rn(hi);
    return *(uint32_t*)&h2;
}
__device__ __forceinline__ uint32_t pack_half2(float a, float b) {
    __half2 h = __floats2half2_rn(a, b);
    return *(uint32_t*)&h;
}

// ---------------------------------------------------------------------------
// Kernel A: segment offsets
// ---------------------------------------------------------------------------
__global__ void offsets_kernel(const int* __restrict__ oi) {
    int e = blockIdx.x * 256 + threadIdx.x;
    if (e >= NEDGE) return;
    int v = oi[e];
    if (e == 0) {
        for (int n = 0; n <= v; n++) g_start[n] = 0;
    } else {
        int p = oi[e - 1];
        for (int n = p + 1; n <= v; n++) g_start[n] = e;
    }
    if (e == NEDGE - 1) {
        for (int n = v + 1; n <= NPTS; n++) g_start[n] = NEDGE;
    }
}

// ---------------------------------------------------------------------------
// Kernel B: W3 transpose + bf16 hi/lo split
// ---------------------------------------------------------------------------
__global__ void prep_w3_kernel(const float* __restrict__ W3) {
    int t = blockIdx.x * 256 + threadIdx.x;
    int k = t >> 6, n = t & 63;
    float v = W3[t];
    __nv_bfloat16 hi = __float2bfloat16_rn(v);
    __nv_bfloat16 lo = __float2bfloat16_rn(v - __bfloat162float(hi));
    g_W3T_hi[n * 1024 + k] = hi;
    g_W3T_lo[n * 1024 + k] = lo;
}

// ---------------------------------------------------------------------------
// Kernel C: tensor-core edge kernel, fp16, lane-per-edge prologue.
// Warp per point, 4 warps/CTA.
// ---------------------------------------------------------------------------
#define PHP 48
#define PXP 144
#define PMP 144
#define WHP 48

__global__ __launch_bounds__(128) void edge_tc_kernel(
    const float* __restrict__ x_in,
    const float* __restrict__ pos_in,
    const float* __restrict__ pos_out,
    const int*   __restrict__ in_index,
    const float* __restrict__ W1,
    const float* __restrict__ W2)
{
    __shared__ __align__(16) float sW1[48];
    __shared__ __align__(16) char s_w2t[64 * WHP];
    __shared__ __align__(16) char s_h [4][64 * PHP];
    __shared__ __align__(16) char s_xT[4][16 * PXP];
    __shared__ __align__(16) char s_M [4][16 * PMP];

    const int tid  = threadIdx.x;
    const int warp = tid >> 5;
    const int lane = tid & 31;

    if (tid < 48) sW1[tid] = W1[tid];
    for (int i = tid; i < 1024; i += 128) {
        int c = i >> 6, nn = i & 63;
        *(__half*)&s_w2t[nn * WHP + c * 2] = __float2half_rn(W2[i]);
    }
    __syncthreads();

    // hoist W2^T B-fragments
    uint32_t bW2[4][4];
    {
        uint32_t rsel = (uint32_t)((lane & 7) + ((lane & 16) ? 8 : 0));
        uint32_t csel = (lane & 8) ? 16u : 0u;
        uint32_t b0 = smem_u32(s_w2t);
#pragma unroll
        for (int j = 0; j < 4; j++) {
            uint32_t a = (rsel + j * 16) * WHP + csel;
            LDMATRIX_X4(bW2[j][0], bW2[j][1], bW2[j][2], bW2[j][3], b0 + a);
        }
    }

    const int n = blockIdx.x * 4 + warp;
    const int start = g_start[n];
    const int cnt   = g_start[n + 1] - start;
    const int nl    = cnt < KMAX ? cnt : KMAX;
    const float inv = (cnt > 0) ? (1.0f / (float)cnt) : 0.0f;
    const int tiles = (nl + 15) >> 4;
    const int epad  = tiles * 16;

    const float po0 = __ldg(pos_out + 3 * n + 0);
    const float po1 = __ldg(pos_out + 3 * n + 1);
    const float po2 = __ldg(pos_out + 3 * n + 2);

    float P[32];
#pragma unroll
    for (int i = 0; i < 32; i++) P[i] = 0.0f;

    const uint32_t shB = smem_u32(s_h[warp]);
    const uint32_t sxB = smem_u32(s_xT[warp]);
    const uint32_t smB = smem_u32(s_M[warp]);

    // ---- batched prologue: one lane per edge (<=2 iterations, usually 1) ----
    for (int e = lane; e < epad; e += 32) {
        float h[16], x[16];
        if (e < nl) {
            int idx  = __ldg(in_index + start + e);
            float d0 = __ldg(pos_in + 3 * idx + 0) - po0;
            float d1 = __ldg(pos_in + 3 * idx + 1) - po1;
            float d2 = __ldg(pos_in + 3 * idx + 2) - po2;
            const float4* xr = (const float4*)(x_in + (size_t)idx * CIN);
            float4 v0 = __ldg(xr), v1 = __ldg(xr + 1), v2 = __ldg(xr + 2), v3 = __ldg(xr + 3);
#pragma unroll
            for (int c = 0; c < 16; c++) {
                float a = fmaf(d0, sW1[c], fmaf(d1, sW1[16 + c], d2 * sW1[32 + c]));
                h[c] = celu_fast(a);
            }
            x[0] = v0.x * inv;  x[1] = v0.y * inv;  x[2] = v0.z * inv;  x[3] = v0.w * inv;
            x[4] = v1.x * inv;  x[5] = v1.y * inv;  x[6] = v1.z * inv;  x[7] = v1.w * inv;
            x[8] = v2.x * inv;  x[9] = v2.y * inv;  x[10] = v2.z * inv; x[11] = v2.w * inv;
            x[12] = v3.x * inv; x[13] = v3.y * inv; x[14] = v3.z * inv; x[15] = v3.w * inv;
        } else {
#pragma unroll
            for (int c = 0; c < 16; c++) { h[c] = 0.0f; x[c] = 0.0f; }
        }
        uint32_t hp[8];
#pragma unroll
        for (int j = 0; j < 8; j++) hp[j] = pack_half2(h[2 * j], h[2 * j + 1]);
        *(uint4*)(s_h[warp] + (uint32_t)e * PHP)      = make_uint4(hp[0], hp[1], hp[2], hp[3]);
        *(uint4*)(s_h[warp] + (uint32_t)e * PHP + 16) = make_uint4(hp[4], hp[5], hp[6], hp[7]);
#pragma unroll
        for (int c = 0; c < 16; c++) {
            *(__half*)(s_xT[warp] + (uint32_t)c * PXP + e * 2) = __float2half_rn(x[c]);
        }
    }
    __syncwarp();

    // ldmatrix address components
    const uint32_t aRowOff = (uint32_t)(lane & 15);
    const uint32_t aColB   = ((lane >> 4) & 1) * 16;
    const uint32_t tRow    = (uint32_t)((lane & 7) + (((lane >> 3) & 1) << 3));
    const uint32_t tCol    = ((lane >> 4) & 1) * 16;
    const int g = lane >> 2;
    const int q = lane & 3;

    for (int t = 0; t < tiles; t++) {
        // ---- GEMM1: M = celu(H @ W2) ----
        {
            uint32_t a[4];
            LDMATRIX_X4(a[0], a[1], a[2], a[3],
                        shB + (t * 16 + aRowOff) * PHP + aColB);
#pragma unroll
            for (int j = 0; j < 4; j++) {
#pragma unroll
                for (int sub = 0; sub < 2; sub++) {
                    const int nt = 2 * j + sub;
                    float C1[4] = {0.f, 0.f, 0.f, 0.f};
                    MMA_FP16(C1, a, bW2[j][2 * sub], bW2[j][2 * sub + 1]);
                    const uint32_t cb = (uint32_t)(nt * 16 + q * 4);
#pragma unroll
                    for (int r2 = 0; r2 < 2; r2++) {
                        float v0 = celu_fast(C1[2 * r2]);
                        float v1 = celu_fast(C1[2 * r2 + 1]);
                        *(uint32_t*)(s_M[warp] + (uint32_t)(g + 8 * r2) * PMP + cb) =
                            pack_half2(v0, v1);
                    }
                }
            }
        }
        __syncwarp();

        // ---- GEMM2: P += X^T @ M ----
        {
            uint32_t ax[4];
            LDMATRIX_X4(ax[0], ax[1], ax[2], ax[3],
                        sxB + aRowOff * PXP + t * 32 + aColB);
#pragma unroll
            for (int pp = 0; pp < 4; pp++) {
                uint32_t b0, b1, b2, b3;
                LDMATRIX_X4_T(b0, b1, b2, b3, smB + tRow * PMP + pp * 32 + tCol);
                MMA_FP16(P + (2 * pp) * 4,     ax, b0, b1);
                MMA_FP16(P + (2 * pp + 1) * 4, ax, b2, b3);
            }
        }
        __syncwarp();
    }

    // ---- store P split (bf16 hi/lo) to gmem ----
    __nv_bfloat16* dh = g_P_hi + (size_t)n * 1024;
    __nv_bfloat16* dl = g_P_lo + (size_t)n * 1024;
#pragma unroll
    for (int nt = 0; nt < 8; nt++) {
#pragma unroll
        for (int r2 = 0; r2 < 2; r2++) {
            float v0 = P[nt * 4 + 2 * r2], v1 = P[nt * 4 + 2 * r2 + 1];
            __nv_bfloat16 h0 = __float2bfloat16_rn(v0);
            __nv_bfloat16 h1 = __float2bfloat16_rn(v1);
            float l0 = v0 - __bfloat162float(h0);
            float l1 = v1 - __bfloat162float(h1);
            int c = g + 8 * r2;
            int m = nt * 8 + 2 * q;
            __nv_bfloat162 ph; ph.x = h0; ph.y = h1;
            *(uint32_t*)(dh + c * 64 + m) = *(uint32_t*)&ph;
            *(uint32_t*)(dl + c * 64 + m) = pack_bf16x2(l0, l1);
        }
    }
}

// ---------------------------------------------------------------------------
// Kernel D: out = P @ W3 + b3. M=128/CTA, 256 thr, 3-stage (2 CTAs/SM).
// ---------------------------------------------------------------------------
#define PITCH_B 80
#define OFF_AHI 0
#define OFF_ALO 10240
#define OFF_BHI 20480
#define OFF_BLO 25600
#define STAGE_BYTES 30720
#define GEMM_SMEM (3 * STAGE_BYTES)

__global__ __launch_bounds__(256) void gemm_mma(
    const float* __restrict__ b3,
    float* __restrict__ out)
{
    extern __shared__ char dsm[];
    const uint32_t sbase = smem_u32(dsm);

    const int tid  = threadIdx.x;
    const int warp = tid >> 5;
    const int lane = tid & 31;
    const int ctaM = blockIdx.x * 128;

    const char* Ahi_g = (const char*)(g_P_hi + (size_t)ctaM * 1024);
    const char* Alo_g = (const char*)(g_P_lo + (size_t)ctaM * 1024);
    const char* Bhi_g = (const char*)g_W3T_hi;
    const char* Blo_g = (const char*)g_W3T_lo;

    auto issue_loads = [&](int kt, int s) {
        uint32_t base = sbase + s * STAGE_BYTES;
        const int kb = kt * 64;
#pragma unroll
        for (int i = 0; i < 2; i++) {
            int idx = tid + i * 256;
            int row = idx >> 2, seg = idx & 3;
            uint32_t d = base + row * PITCH_B + seg * 16;
            size_t gofs = (size_t)row * 2048 + kb + seg * 16;
            cp16(d + OFF_AHI, Ahi_g + gofs);
            cp16(d + OFF_ALO, Alo_g + gofs);
        }
        {
            int row = tid >> 2, seg = tid & 3;
            uint32_t d = base + row * PITCH_B + seg * 16;
            size_t gofs = (size_t)row * 2048 + kb + seg * 16;
            cp16(d + OFF_BHI, Bhi_g + gofs);
            cp16(d + OFF_BLO, Blo_g + gofs);
        }
    };

    float C[8][4];
#pragma unroll
    for (int nt = 0; nt < 8; nt++)
#pragma unroll
        for (int i = 0; i < 4; i++) C[nt][i] = 0.0f;

    const uint32_t aRow  = warp * 16 + (lane & 15);
    const uint32_t aColB = ((lane >> 4) & 1) * 16;
    const uint32_t bRow  = (lane & 7) + ((lane & 16) ? 8 : 0);
    const uint32_t bColB = (lane & 8) ? 16 : 0;

    issue_loads(0, 0); CP_COMMIT();
    issue_loads(1, 1); CP_COMMIT();

    int scur = 0;   // stage of kt
    for (int kt = 0; kt < 32; kt++) {
        CP_WAIT(1);
        __syncthreads();
        if (kt + 2 < 32) {
            int snext = scur + 2; if (snext >= 3) snext -= 3;
            issue_loads(kt + 2, snext);
        }
        CP_COMMIT();

        const uint32_t base = sbase + scur * STAGE_BYTES;
#pragma unroll
        for (int ks = 0; ks < 2; ks++) {
            const uint32_t kOffB = ks * 32;
            uint32_t ah[4], al[4];
            uint32_t aa = base + aRow * PITCH_B + kOffB + aColB;
            LDMATRIX_X4(ah[0], ah[1], ah[2], ah[3], aa + OFF_AHI);
            LDMATRIX_X4(al[0], al[1], al[2], al[3], aa + OFF_ALO);
#pragma unroll
            for (int p = 0; p < 4; p++) {
                uint32_t bh0, bh1, bh2, bh3, bl0, bl1, bl2, bl3;
                uint32_t ba = base + (p * 16 + bRow) * PITCH_B + kOffB + bColB;
                LDMATRIX_X4(bh0, bh1, bh2, bh3, ba + OFF_BHI);
                LDMATRIX_X4(bl0, bl1, bl2, bl3, ba + OFF_BLO);
                MMA_BF16(C[2 * p],     ah, bh0, bh1);
                MMA_BF16(C[2 * p],     al, bh0, bh1);
                MMA_BF16(C[2 * p],     ah, bl0, bl1);
                MMA_BF16(C[2 * p + 1], ah, bh2, bh3);
                MMA_BF16(C[2 * p + 1], al, bh2, bh3);
                MMA_BF16(C[2 * p + 1], ah, bl2, bl3);
            }
        }
        if (++scur == 3) scur = 0;
    }

    const int g  = lane >> 2;
    const int q2 = (lane & 3) * 2;
    const int rowBase = ctaM + warp * 16;
#pragma unroll
    for (int nt = 0; nt < 8; nt++) {
        const int col = nt * 8 + q2;
        float2 bb = *(const float2*)(b3 + col);
        float2 v0, v1;
        v0.x = C[nt][0] + bb.x;
        v0.y = C[nt][1] + bb.y;
        v1.x = C[nt][2] + bb.x;
        v1.y = C[nt][3] + bb.y;
        *(float2*)(out + (size_t)(rowBase + g) * COUT + col) = v0;
        *(float2*)(out + (size_t)(rowBase + g + 8) * COUT + col) = v1;
    }
}

// ---------------------------------------------------------------------------
extern "C" void kernel_launch(void* const* d_in, const int* in_sizes, int n_in,
                              void* d_out, int out_size) {
    const float* x_in      = (const float*)d_in[0];
    const float* pos_in    = (const float*)d_in[1];
    const float* pos_out   = (const float*)d_in[2];
    const int*   in_index  = (const int*)d_in[3];
    const int*   out_index = (const int*)d_in[4];
    const float* W1        = (const float*)d_in[5];
    const float* W2        = (const float*)d_in[6];
    const float* W3        = (const float*)d_in[7];
    const float* b3        = (const float*)d_in[8];
    float* out = (float*)d_out;

    cudaFuncSetAttribute(gemm_mma, cudaFuncAttributeMaxDynamicSharedMemorySize, GEMM_SMEM);

    offsets_kernel<<<(NEDGE + 255) / 256, 256>>>(out_index);
    prep_w3_kernel<<<(1024 * 64) / 256, 256>>>(W3);
    edge_tc_kernel<<<NPTS / 4, 128>>>(x_in, pos_in, pos_out, in_index, W1, W2);
    gemm_mma<<<NPTS / 128, 256, GEMM_SMEM>>>(b3, out);
}

// round 7
// speedup vs baseline: 2.3661x; 1.0676x over previous
#include <cuda_runtime.h>
#include <cuda_bf16.h>
#include <cuda_fp16.h>
#include <math.h>
#include <stdint.h>

#define NPTS  32768
#define NEDGE 786432
#define CIN   16
#define CMID  64
#define COUT  64
#define KMAX  64

// ---------------- device scratch ----------------
__device__ __half g_P_h[(size_t)NPTS * 1024];     // P fp16, [N,1024]
__device__ __half g_W3T_hi[COUT * 1024];          // W3^T fp16 split, [64][1024]
__device__ __half g_W3T_lo[COUT * 1024];
__device__ int g_start[NPTS + 1];

__device__ __forceinline__ float celu_fast(float x) {
    return x > 0.0f ? x : (__expf(x) - 1.0f);
}
__device__ __forceinline__ uint32_t smem_u32(const void* p) {
    uint32_t a;
    asm("{ .reg .u64 t; cvta.to.shared.u64 t, %1; cvt.u32.u64 %0, t; }" : "=r"(a) : "l"(p));
    return a;
}
__device__ __forceinline__ void cp16(uint32_t dst, const void* src) {
    asm volatile("cp.async.cg.shared.global [%0], [%1], 16;" :: "r"(dst), "l"(src) : "memory");
}
#define CP_COMMIT() asm volatile("cp.async.commit_group;" ::: "memory")
#define CP_WAIT(n)  asm volatile("cp.async.wait_group %0;" :: "n"(n) : "memory")

#define LDMATRIX_X4(r0, r1, r2, r3, addr) \
    asm volatile("ldmatrix.sync.aligned.m8n8.x4.shared.b16 {%0,%1,%2,%3}, [%4];" \
                 : "=r"(r0), "=r"(r1), "=r"(r2), "=r"(r3) : "r"(addr))
#define LDMATRIX_X4_T(r0, r1, r2, r3, addr) \
    asm volatile("ldmatrix.sync.aligned.m8n8.x4.trans.shared.b16 {%0,%1,%2,%3}, [%4];" \
                 : "=r"(r0), "=r"(r1), "=r"(r2), "=r"(r3) : "r"(addr))

#define MMA_FP16(C, A, B0, B1) \
    asm volatile("mma.sync.aligned.m16n8k16.row.col.f32.f16.f16.f32 " \
        "{%0,%1,%2,%3}, {%4,%5,%6,%7}, {%8,%9}, {%0,%1,%2,%3};" \
        : "+f"((C)[0]), "+f"((C)[1]), "+f"((C)[2]), "+f"((C)[3]) \
        : "r"((A)[0]), "r"((A)[1]), "r"((A)[2]), "r"((A)[3]), "r"(B0), "r"(B1))

__device__ __forceinline__ uint32_t pack_half2(float a, float b) {
    __half2 h = __floats2half2_rn(a, b);
    return *(uint32_t*)&h;
}

// ---------------------------------------------------------------------------
// Kernel A: segment offsets
// ---------------------------------------------------------------------------
__global__ void offsets_kernel(const int* __restrict__ oi) {
    int e = blockIdx.x * 256 + threadIdx.x;
    if (e >= NEDGE) return;
    int v = oi[e];
    if (e == 0) {
        for (int n = 0; n <= v; n++) g_start[n] = 0;
    } else {
        int p = oi[e - 1];
        for (int n = p + 1; n <= v; n++) g_start[n] = e;
    }
    if (e == NEDGE - 1) {
        for (int n = v + 1; n <= NPTS; n++) g_start[n] = NEDGE;
    }
}

// ---------------------------------------------------------------------------
// Kernel B: W3 transpose + fp16 hi/lo split
// ---------------------------------------------------------------------------
__global__ void prep_w3_kernel(const float* __restrict__ W3) {
    int t = blockIdx.x * 256 + threadIdx.x;
    int k = t >> 6, n = t & 63;
    float v = W3[t];
    __half hi = __float2half_rn(v);
    __half lo = __float2half_rn(v - __half2float(hi));
    g_W3T_hi[n * 1024 + k] = hi;
    g_W3T_lo[n * 1024 + k] = lo;
}

// ---------------------------------------------------------------------------
// Kernel C: tensor-core edge kernel, fp16. Warp per point, 4 warps/CTA.
// Phase 1: prologue (all edges). Phase 2: all GEMM1 tiles. Phase 3: all GEMM2.
// ---------------------------------------------------------------------------
#define PHP 48
#define PXP 144
#define PMP 144
#define WHP 48

__global__ __launch_bounds__(128) void edge_tc_kernel(
    const float* __restrict__ x_in,
    const float* __restrict__ pos_in,
    const float* __restrict__ pos_out,
    const int*   __restrict__ in_index,
    const float* __restrict__ W1,
    const float* __restrict__ W2)
{
    __shared__ __align__(16) float sW1[48];
    __shared__ __align__(16) char s_w2t[64 * WHP];
    __shared__ __align__(16) char s_h [4][64 * PHP];
    __shared__ __align__(16) char s_xT[4][16 * PXP];
    __shared__ __align__(16) char s_M [4][64 * PMP];   // all tiles

    const int tid  = threadIdx.x;
    const int warp = tid >> 5;
    const int lane = tid & 31;

    if (tid < 48) sW1[tid] = W1[tid];
    for (int i = tid; i < 1024; i += 128) {
        int c = i >> 6, nn = i & 63;
        *(__half*)&s_w2t[nn * WHP + c * 2] = __float2half_rn(W2[i]);
    }
    __syncthreads();

    // hoist W2^T B-fragments
    uint32_t bW2[4][4];
    {
        uint32_t rsel = (uint32_t)((lane & 7) + ((lane & 16) ? 8 : 0));
        uint32_t csel = (lane & 8) ? 16u : 0u;
        uint32_t b0 = smem_u32(s_w2t);
#pragma unroll
        for (int j = 0; j < 4; j++) {
            uint32_t a = (rsel + j * 16) * WHP + csel;
            LDMATRIX_X4(bW2[j][0], bW2[j][1], bW2[j][2], bW2[j][3], b0 + a);
        }
    }

    const int n = blockIdx.x * 4 + warp;
    const int start = g_start[n];
    const int cnt   = g_start[n + 1] - start;
    const int nl    = cnt < KMAX ? cnt : KMAX;
    const float inv = (cnt > 0) ? (1.0f / (float)cnt) : 0.0f;
    const int tiles = (nl + 15) >> 4;
    const int epad  = tiles * 16;

    const float po0 = __ldg(pos_out + 3 * n + 0);
    const float po1 = __ldg(pos_out + 3 * n + 1);
    const float po2 = __ldg(pos_out + 3 * n + 2);

    float P[32];
#pragma unroll
    for (int i = 0; i < 32; i++) P[i] = 0.0f;

    const uint32_t shB = smem_u32(s_h[warp]);
    const uint32_t sxB = smem_u32(s_xT[warp]);
    const uint32_t smB = smem_u32(s_M[warp]);

    // ---- phase 1: prologue, one lane per edge ----
    for (int e = lane; e < epad; e += 32) {
        float h[16], x[16];
        if (e < nl) {
            int idx  = __ldg(in_index + start + e);
            float d0 = __ldg(pos_in + 3 * idx + 0) - po0;
            float d1 = __ldg(pos_in + 3 * idx + 1) - po1;
            float d2 = __ldg(pos_in + 3 * idx + 2) - po2;
            const float4* xr = (const float4*)(x_in + (size_t)idx * CIN);
            float4 v0 = __ldg(xr), v1 = __ldg(xr + 1), v2 = __ldg(xr + 2), v3 = __ldg(xr + 3);
#pragma unroll
            for (int c = 0; c < 16; c++) {
                float a = fmaf(d0, sW1[c], fmaf(d1, sW1[16 + c], d2 * sW1[32 + c]));
                h[c] = celu_fast(a);
            }
            x[0] = v0.x * inv;  x[1] = v0.y * inv;  x[2] = v0.z * inv;  x[3] = v0.w * inv;
            x[4] = v1.x * inv;  x[5] = v1.y * inv;  x[6] = v1.z * inv;  x[7] = v1.w * inv;
            x[8] = v2.x * inv;  x[9] = v2.y * inv;  x[10] = v2.z * inv; x[11] = v2.w * inv;
            x[12] = v3.x * inv; x[13] = v3.y * inv; x[14] = v3.z * inv; x[15] = v3.w * inv;
        } else {
#pragma unroll
            for (int c = 0; c < 16; c++) { h[c] = 0.0f; x[c] = 0.0f; }
        }
        uint32_t hp[8];
#pragma unroll
        for (int j = 0; j < 8; j++) hp[j] = pack_half2(h[2 * j], h[2 * j + 1]);
        *(uint4*)(s_h[warp] + (uint32_t)e * PHP)      = make_uint4(hp[0], hp[1], hp[2], hp[3]);
        *(uint4*)(s_h[warp] + (uint32_t)e * PHP + 16) = make_uint4(hp[4], hp[5], hp[6], hp[7]);
#pragma unroll
        for (int c = 0; c < 16; c++) {
            *(__half*)(s_xT[warp] + (uint32_t)c * PXP + e * 2) = __float2half_rn(x[c]);
        }
    }
    __syncwarp();

    const uint32_t aRowOff = (uint32_t)(lane & 15);
    const uint32_t aColB   = ((lane >> 4) & 1) * 16;
    const uint32_t tRow    = (uint32_t)((lane & 7) + (((lane >> 3) & 1) << 3));
    const uint32_t tCol    = ((lane >> 4) & 1) * 16;
    const int g = lane >> 2;
    const int q = lane & 3;

    // ---- phase 2: GEMM1 for all tiles: M = celu(H @ W2) ----
    for (int t = 0; t < tiles; t++) {
        uint32_t a[4];
        LDMATRIX_X4(a[0], a[1], a[2], a[3],
                    shB + (t * 16 + aRowOff) * PHP + aColB);
#pragma unroll
        for (int j = 0; j < 4; j++) {
#pragma unroll
            for (int sub = 0; sub < 2; sub++) {
                const int nt = 2 * j + sub;
                float C1[4] = {0.f, 0.f, 0.f, 0.f};
                MMA_FP16(C1, a, bW2[j][2 * sub], bW2[j][2 * sub + 1]);
                const uint32_t cb = (uint32_t)(nt * 16 + q * 4);
#pragma unroll
                for (int r2 = 0; r2 < 2; r2++) {
                    float v0 = celu_fast(C1[2 * r2]);
                    float v1 = celu_fast(C1[2 * r2 + 1]);
                    *(uint32_t*)(s_M[warp] + (uint32_t)(t * 16 + g + 8 * r2) * PMP + cb) =
                        pack_half2(v0, v1);
                }
            }
        }
    }
    __syncwarp();

    // ---- phase 3: GEMM2 for all tiles: P += X^T @ M ----
    for (int t = 0; t < tiles; t++) {
        uint32_t ax[4];
        LDMATRIX_X4(ax[0], ax[1], ax[2], ax[3],
                    sxB + aRowOff * PXP + t * 32 + aColB);
#pragma unroll
        for (int pp = 0; pp < 4; pp++) {
            uint32_t b0, b1, b2, b3;
            LDMATRIX_X4_T(b0, b1, b2, b3,
                          smB + (t * 16 + tRow) * PMP + pp * 32 + tCol);
            MMA_FP16(P + (2 * pp) * 4,     ax, b0, b1);
            MMA_FP16(P + (2 * pp + 1) * 4, ax, b2, b3);
        }
    }

    // ---- store P fp16 to gmem ----
    __half* dp = g_P_h + (size_t)n * 1024;
#pragma unroll
    for (int nt = 0; nt < 8; nt++) {
#pragma unroll
        for (int r2 = 0; r2 < 2; r2++) {
            int c = g + 8 * r2;
            int m = nt * 8 + 2 * q;
            *(uint32_t*)(dp + c * 64 + m) =
                pack_half2(P[nt * 4 + 2 * r2], P[nt * 4 + 2 * r2 + 1]);
        }
    }
}

// ---------------------------------------------------------------------------
// Kernel D: out = P @ W3 + b3. M=128/CTA, 256 thr, 3-stage (3 CTAs/SM).
// A = P fp16 single; B = W3 fp16 hi/lo (2 products).
// ---------------------------------------------------------------------------
#define PITCH_B 80
#define OFF_A   0
#define OFF_BHI 10240
#define OFF_BLO 15360
#define STAGE_BYTES 20480
#define GEMM_SMEM (3 * STAGE_BYTES)

__global__ __launch_bounds__(256) void gemm_mma(
    const float* __restrict__ b3,
    float* __restrict__ out)
{
    extern __shared__ char dsm[];
    const uint32_t sbase = smem_u32(dsm);

    const int tid  = threadIdx.x;
    const int warp = tid >> 5;
    const int lane = tid & 31;
    const int ctaM = blockIdx.x * 128;

    const char* A_g   = (const char*)(g_P_h + (size_t)ctaM * 1024);
    const char* Bhi_g = (const char*)g_W3T_hi;
    const char* Blo_g = (const char*)g_W3T_lo;

    auto issue_loads = [&](int kt, int s) {
        uint32_t base = sbase + s * STAGE_BYTES;
        const int kb = kt * 64;
#pragma unroll
        for (int i = 0; i < 2; i++) {
            int idx = tid + i * 256;          // 512 -> A: 128 rows x 4 segs
            int row = idx >> 2, seg = idx & 3;
            uint32_t d = base + OFF_A + row * PITCH_B + seg * 16;
            cp16(d, A_g + (size_t)row * 2048 + kb + seg * 16);
        }
        {
            int row = tid >> 2, seg = tid & 3; // 64 rows x 4 segs
            uint32_t d = base + row * PITCH_B + seg * 16;
            size_t gofs = (size_t)row * 2048 + kb + seg * 16;
            cp16(d + OFF_BHI, Bhi_g + gofs);
            cp16(d + OFF_BLO, Blo_g + gofs);
        }
    };

    float C[8][4];
#pragma unroll
    for (int nt = 0; nt < 8; nt++)
#pragma unroll
        for (int i = 0; i < 4; i++) C[nt][i] = 0.0f;

    const uint32_t aRow  = warp * 16 + (lane & 15);
    const uint32_t aColB = ((lane >> 4) & 1) * 16;
    const uint32_t bRow  = (lane & 7) + ((lane & 16) ? 8 : 0);
    const uint32_t bColB = (lane & 8) ? 16 : 0;

    issue_loads(0, 0); CP_COMMIT();
    issue_loads(1, 1); CP_COMMIT();

    int scur = 0;
    for (int kt = 0; kt < 32; kt++) {
        CP_WAIT(1);
        __syncthreads();
        if (kt + 2 < 32) {
            int snext = scur + 2; if (snext >= 3) snext -= 3;
            issue_loads(kt + 2, snext);
        }
        CP_COMMIT();

        const uint32_t base = sbase + scur * STAGE_BYTES;
#pragma unroll
        for (int ks = 0; ks < 2; ks++) {
            const uint32_t kOffB = ks * 32;
            uint32_t a[4];
            LDMATRIX_X4(a[0], a[1], a[2], a[3],
                        base + OFF_A + aRow * PITCH_B + kOffB + aColB);
#pragma unroll
            for (int p = 0; p < 4; p++) {
                uint32_t bh0, bh1, bh2, bh3, bl0, bl1, bl2, bl3;
                uint32_t ba = base + (p * 16 + bRow) * PITCH_B + kOffB + bColB;
                LDMATRIX_X4(bh0, bh1, bh2, bh3, ba + OFF_BHI);
                LDMATRIX_X4(bl0, bl1, bl2, bl3, ba + OFF_BLO);
                MMA_FP16(C[2 * p],     a, bh0, bh1);
                MMA_FP16(C[2 * p],     a, bl0, bl1);
                MMA_FP16(C[2 * p + 1], a, bh2, bh3);
                MMA_FP16(C[2 * p + 1], a, bl2, bl3);
            }
        }
        if (++scur == 3) scur = 0;
    }

    const int g  = lane >> 2;
    const int q2 = (lane & 3) * 2;
    const int rowBase = ctaM + warp * 16;
#pragma unroll
    for (int nt = 0; nt < 8; nt++) {
        const int col = nt * 8 + q2;
        float2 bb = *(const float2*)(b3 + col);
        float2 v0, v1;
        v0.x = C[nt][0] + bb.x;
        v0.y = C[nt][1] + bb.y;
        v1.x = C[nt][2] + bb.x;
        v1.y = C[nt][3] + bb.y;
        *(float2*)(out + (size_t)(rowBase + g) * COUT + col) = v0;
        *(float2*)(out + (size_t)(rowBase + g + 8) * COUT + col) = v1;
    }
}

// ---------------------------------------------------------------------------
extern "C" void kernel_launch(void* const* d_in, const int* in_sizes, int n_in,
                              void* d_out, int out_size) {
    const float* x_in      = (const float*)d_in[0];
    const float* pos_in    = (const float*)d_in[1];
    const float* pos_out   = (const float*)d_in[2];
    const int*   in_index  = (const int*)d_in[3];
    const int*   out_index = (const int*)d_in[4];
    const float* W1        = (const float*)d_in[5];
    const float* W2        = (const float*)d_in[6];
    const float* W3        = (const float*)d_in[7];
    const float* b3        = (const float*)d_in[8];
    float* out = (float*)d_out;

    cudaFuncSetAttribute(gemm_mma, cudaFuncAttributeMaxDynamicSharedMemorySize, GEMM_SMEM);

    offsets_kernel<<<(NEDGE + 255) / 256, 256>>>(out_index);
    prep_w3_kernel<<<(1024 * 64) / 256, 256>>>(W3);
    edge_tc_kernel<<<NPTS / 4, 128>>>(x_in, pos_in, pos_out, in_index, W1, W2);
    gemm_mma<<<NPTS / 128, 256, GEMM_SMEM>>>(b3, out);
}

// round 8
// speedup vs baseline: 2.7518x; 1.1630x over previous
#include <cuda_runtime.h>
#include <cuda_bf16.h>
#include <cuda_fp16.h>
#include <math.h>
#include <stdint.h>

#define NPTS  32768
#define NEDGE 786432
#define CIN   16
#define CMID  64
#define COUT  64
#define KMAX  64

// ---------------- device scratch ----------------
__device__ __half g_P_h[(size_t)NPTS * 1024];
__device__ __half g_W3T_hi[COUT * 1024];
__device__ __half g_W3T_lo[COUT * 1024];
__device__ int g_start[NPTS + 1];

// branchless CELU: fmax(x,0) - 1 + exp(fmin(x,0));  exp(0)=1 exactly -> x>=0 gives x
__device__ __forceinline__ float celu_fast(float x) {
    return fmaxf(x, 0.0f) - 1.0f + __expf(fminf(x, 0.0f));
}
__device__ __forceinline__ uint32_t smem_u32(const void* p) {
    uint32_t a;
    asm("{ .reg .u64 t; cvta.to.shared.u64 t, %1; cvt.u32.u64 %0, t; }" : "=r"(a) : "l"(p));
    return a;
}
__device__ __forceinline__ void cp16(uint32_t dst, const void* src) {
    asm volatile("cp.async.cg.shared.global [%0], [%1], 16;" :: "r"(dst), "l"(src) : "memory");
}
#define CP_COMMIT() asm volatile("cp.async.commit_group;" ::: "memory")
#define CP_WAIT(n)  asm volatile("cp.async.wait_group %0;" :: "n"(n) : "memory")

#define LDMATRIX_X4(r0, r1, r2, r3, addr) \
    asm volatile("ldmatrix.sync.aligned.m8n8.x4.shared.b16 {%0,%1,%2,%3}, [%4];" \
                 : "=r"(r0), "=r"(r1), "=r"(r2), "=r"(r3) : "r"(addr))
#define LDMATRIX_X4_T(r0, r1, r2, r3, addr) \
    asm volatile("ldmatrix.sync.aligned.m8n8.x4.trans.shared.b16 {%0,%1,%2,%3}, [%4];" \
                 : "=r"(r0), "=r"(r1), "=r"(r2), "=r"(r3) : "r"(addr))

#define MMA_FP16(C, A, B0, B1) \
    asm volatile("mma.sync.aligned.m16n8k16.row.col.f32.f16.f16.f32 " \
        "{%0,%1,%2,%3}, {%4,%5,%6,%7}, {%8,%9}, {%0,%1,%2,%3};" \
        : "+f"((C)[0]), "+f"((C)[1]), "+f"((C)[2]), "+f"((C)[3]) \
        : "r"((A)[0]), "r"((A)[1]), "r"((A)[2]), "r"((A)[3]), "r"(B0), "r"(B1))

__device__ __forceinline__ uint32_t pack_half2(float a, float b) {
    __half2 h = __floats2half2_rn(a, b);
    return *(uint32_t*)&h;
}

// ---------------------------------------------------------------------------
// Kernel A: segment offsets
// ---------------------------------------------------------------------------
__global__ void offsets_kernel(const int* __restrict__ oi) {
    int e = blockIdx.x * 256 + threadIdx.x;
    if (e >= NEDGE) return;
    int v = oi[e];
    if (e == 0) {
        for (int n = 0; n <= v; n++) g_start[n] = 0;
    } else {
        int p = oi[e - 1];
        for (int n = p + 1; n <= v; n++) g_start[n] = e;
    }
    if (e == NEDGE - 1) {
        for (int n = v + 1; n <= NPTS; n++) g_start[n] = NEDGE;
    }
}

// ---------------------------------------------------------------------------
// Kernel B: W3 transpose + fp16 hi/lo split
// ---------------------------------------------------------------------------
__global__ void prep_w3_kernel(const float* __restrict__ W3) {
    int t = blockIdx.x * 256 + threadIdx.x;
    int k = t >> 6, n = t & 63;
    float v = W3[t];
    __half hi = __float2half_rn(v);
    __half lo = __float2half_rn(v - __half2float(hi));
    g_W3T_hi[n * 1024 + k] = hi;
    g_W3T_lo[n * 1024 + k] = lo;
}

// ---------------------------------------------------------------------------
// Kernel C: tensor-core edge kernel, fp16. Warp per point, 4 warps/CTA.
// Early index prefetch; per-tile M buffer (low smem -> high occupancy).
// ---------------------------------------------------------------------------
#define PHP 48
#define PXP 144
#define PMP 144
#define WHP 48

__global__ __launch_bounds__(128) void edge_tc_kernel(
    const float* __restrict__ x_in,
    const float* __restrict__ pos_in,
    const float* __restrict__ pos_out,
    const int*   __restrict__ in_index,
    const float* __restrict__ W1,
    const float* __restrict__ W2)
{
    __shared__ __align__(16) float sW1[48];
    __shared__ __align__(16) char s_w2t[64 * WHP];
    __shared__ __align__(16) char s_h [4][64 * PHP];
    __shared__ __align__(16) char s_xT[4][16 * PXP];
    __shared__ __align__(16) char s_M [4][16 * PMP];   // per-tile

    const int tid  = threadIdx.x;
    const int warp = tid >> 5;
    const int lane = tid & 31;

    // ---- early loads: issue BEFORE the CTA-wide smem setup/sync ----
    const int n = blockIdx.x * 4 + warp;
    const int start = __ldg(g_start + n);
    const int cnt   = __ldg(g_start + n + 1) - start;
    const int nl    = cnt < KMAX ? cnt : KMAX;
    const int tiles = (nl + 15) >> 4;
    const int epad  = tiles * 16;
    const float inv = (cnt > 0) ? (1.0f / (float)cnt) : 0.0f;

    const float po0 = __ldg(pos_out + 3 * n + 0);
    const float po1 = __ldg(pos_out + 3 * n + 1);
    const float po2 = __ldg(pos_out + 3 * n + 2);

    int myidx[2];
#pragma unroll
    for (int it = 0; it < 2; it++) {
        int e = lane + 32 * it;
        myidx[it] = (e < nl) ? __ldg(in_index + start + e) : -1;
    }

    // ---- CTA-shared weight staging ----
    if (tid < 48) sW1[tid] = W1[tid];
    for (int i = tid; i < 1024; i += 128) {
        int c = i >> 6, nn = i & 63;
        *(__half*)&s_w2t[nn * WHP + c * 2] = __float2half_rn(W2[i]);
    }
    __syncthreads();

    // hoist W2^T B-fragments
    uint32_t bW2[4][4];
    {
        uint32_t rsel = (uint32_t)((lane & 7) + ((lane & 16) ? 8 : 0));
        uint32_t csel = (lane & 8) ? 16u : 0u;
        uint32_t b0 = smem_u32(s_w2t);
#pragma unroll
        for (int j = 0; j < 4; j++) {
            uint32_t a = (rsel + j * 16) * WHP + csel;
            LDMATRIX_X4(bW2[j][0], bW2[j][1], bW2[j][2], bW2[j][3], b0 + a);
        }
    }

    float P[32];
#pragma unroll
    for (int i = 0; i < 32; i++) P[i] = 0.0f;

    const uint32_t shB = smem_u32(s_h[warp]);
    const uint32_t sxB = smem_u32(s_xT[warp]);
    const uint32_t smB = smem_u32(s_M[warp]);

    // ---- prologue: one lane per edge, raw x (inv applied at store) ----
#pragma unroll
    for (int it = 0; it < 2; it++) {
        int e = lane + 32 * it;
        if (e >= epad) break;
        float h[16], x[16];
        const int idx = myidx[it];
        if (idx >= 0) {
            float d0 = __ldg(pos_in + 3 * idx + 0) - po0;
            float d1 = __ldg(pos_in + 3 * idx + 1) - po1;
            float d2 = __ldg(pos_in + 3 * idx + 2) - po2;
            const float4* xr = (const float4*)(x_in + (size_t)idx * CIN);
            float4 v0 = __ldg(xr), v1 = __ldg(xr + 1), v2 = __ldg(xr + 2), v3 = __ldg(xr + 3);
#pragma unroll
            for (int c = 0; c < 16; c++) {
                float a = fmaf(d0, sW1[c], fmaf(d1, sW1[16 + c], d2 * sW1[32 + c]));
                h[c] = celu_fast(a);
            }
            x[0] = v0.x;  x[1] = v0.y;  x[2] = v0.z;  x[3] = v0.w;
            x[4] = v1.x;  x[5] = v1.y;  x[6] = v1.z;  x[7] = v1.w;
            x[8] = v2.x;  x[9] = v2.y;  x[10] = v2.z; x[11] = v2.w;
            x[12] = v3.x; x[13] = v3.y; x[14] = v3.z; x[15] = v3.w;
        } else {
#pragma unroll
            for (int c = 0; c < 16; c++) { h[c] = 0.0f; x[c] = 0.0f; }
        }
        uint32_t hp[8];
#pragma unroll
        for (int j = 0; j < 8; j++) hp[j] = pack_half2(h[2 * j], h[2 * j + 1]);
        *(uint4*)(s_h[warp] + (uint32_t)e * PHP)      = make_uint4(hp[0], hp[1], hp[2], hp[3]);
        *(uint4*)(s_h[warp] + (uint32_t)e * PHP + 16) = make_uint4(hp[4], hp[5], hp[6], hp[7]);
#pragma unroll
        for (int c = 0; c < 16; c++) {
            *(__half*)(s_xT[warp] + (uint32_t)c * PXP + e * 2) = __float2half_rn(x[c]);
        }
    }
    __syncwarp();

    const uint32_t aRowOff = (uint32_t)(lane & 15);
    const uint32_t aColB   = ((lane >> 4) & 1) * 16;
    const uint32_t tRow    = (uint32_t)((lane & 7) + (((lane >> 3) & 1) << 3));
    const uint32_t tCol    = ((lane >> 4) & 1) * 16;
    const int g = lane >> 2;
    const int q = lane & 3;

    for (int t = 0; t < tiles; t++) {
        // ---- GEMM1: M = celu(H @ W2) ----
        {
            uint32_t a[4];
            LDMATRIX_X4(a[0], a[1], a[2], a[3],
                        shB + (t * 16 + aRowOff) * PHP + aColB);
#pragma unroll
            for (int j = 0; j < 4; j++) {
#pragma unroll
                for (int sub = 0; sub < 2; sub++) {
                    const int nt = 2 * j + sub;
                    float C1[4] = {0.f, 0.f, 0.f, 0.f};
                    MMA_FP16(C1, a, bW2[j][2 * sub], bW2[j][2 * sub + 1]);
                    const uint32_t cb = (uint32_t)(nt * 16 + q * 4);
#pragma unroll
                    for (int r2 = 0; r2 < 2; r2++) {
                        float v0 = celu_fast(C1[2 * r2]);
                        float v1 = celu_fast(C1[2 * r2 + 1]);
                        *(uint32_t*)(s_M[warp] + (uint32_t)(g + 8 * r2) * PMP + cb) =
                            pack_half2(v0, v1);
                    }
                }
            }
        }
        __syncwarp();

        // ---- GEMM2: P += X^T @ M ----
        {
            uint32_t ax[4];
            LDMATRIX_X4(ax[0], ax[1], ax[2], ax[3],
                        sxB + aRowOff * PXP + t * 32 + aColB);
#pragma unroll
            for (int pp = 0; pp < 4; pp++) {
                uint32_t b0, b1, b2, b3;
                LDMATRIX_X4_T(b0, b1, b2, b3, smB + tRow * PMP + pp * 32 + tCol);
                MMA_FP16(P + (2 * pp) * 4,     ax, b0, b1);
                MMA_FP16(P + (2 * pp + 1) * 4, ax, b2, b3);
            }
        }
        __syncwarp();
    }

    // ---- store P * inv (fp16) ----
    __half* dp = g_P_h + (size_t)n * 1024;
#pragma unroll
    for (int nt = 0; nt < 8; nt++) {
#pragma unroll
        for (int r2 = 0; r2 < 2; r2++) {
            int c = g + 8 * r2;
            int m = nt * 8 + 2 * q;
            *(uint32_t*)(dp + c * 64 + m) =
                pack_half2(P[nt * 4 + 2 * r2] * inv, P[nt * 4 + 2 * r2 + 1] * inv);
        }
    }
}

// ---------------------------------------------------------------------------
// Kernel D: out = P @ W3 + b3. M=64/CTA, grid 512, 256 thr (4x2 warp grid),
// 3-stage cp.async, 15KB stages -> 5 CTAs/SM.
// ---------------------------------------------------------------------------
#define PITCH_B 80
#define OFF_A   0
#define OFF_BHI 5120
#define OFF_BLO 10240
#define STAGE_BYTES 15360
#define GEMM_SMEM (3 * STAGE_BYTES)

__global__ __launch_bounds__(256) void gemm_mma(
    const float* __restrict__ b3,
    float* __restrict__ out)
{
    extern __shared__ char dsm[];
    const uint32_t sbase = smem_u32(dsm);

    const int tid  = threadIdx.x;
    const int warp = tid >> 5;
    const int lane = tid & 31;
    const int ctaM = blockIdx.x * 64;
    const int warpM = (warp & 3) * 16;
    const int warpN = (warp >> 2) * 32;

    const char* A_g   = (const char*)(g_P_h + (size_t)ctaM * 1024);
    const char* Bhi_g = (const char*)g_W3T_hi;
    const char* Blo_g = (const char*)g_W3T_lo;

    auto issue_loads = [&](int kt, int s) {
        uint32_t base = sbase + s * STAGE_BYTES;
        const int kb = kt * 64;
        {
            int row = tid >> 2, seg = tid & 3;   // 64 A rows x 4 segs
            uint32_t d = base + OFF_A + row * PITCH_B + seg * 16;
            cp16(d, A_g + (size_t)row * 2048 + kb + seg * 16);
        }
        {
            int row = tid >> 2, seg = tid & 3;   // 64 B rows x 4 segs
            uint32_t d = base + row * PITCH_B + seg * 16;
            size_t gofs = (size_t)row * 2048 + kb + seg * 16;
            cp16(d + OFF_BHI, Bhi_g + gofs);
            cp16(d + OFF_BLO, Blo_g + gofs);
        }
    };

    float C[4][4];
#pragma unroll
    for (int nt = 0; nt < 4; nt++)
#pragma unroll
        for (int i = 0; i < 4; i++) C[nt][i] = 0.0f;

    const uint32_t aRow  = warpM + (lane & 15);
    const uint32_t aColB = ((lane >> 4) & 1) * 16;
    const uint32_t bRow  = (lane & 7) + ((lane & 16) ? 8 : 0);
    const uint32_t bColB = (lane & 8) ? 16 : 0;

    issue_loads(0, 0); CP_COMMIT();
    issue_loads(1, 1); CP_COMMIT();

    int scur = 0;
    for (int kt = 0; kt < 32; kt++) {
        CP_WAIT(1);
        __syncthreads();
        if (kt + 2 < 32) {
            int snext = scur + 2; if (snext >= 3) snext -= 3;
            issue_loads(kt + 2, snext);
        }
        CP_COMMIT();

        const uint32_t base = sbase + scur * STAGE_BYTES;
#pragma unroll
        for (int ks = 0; ks < 2; ks++) {
            const uint32_t kOffB = ks * 32;
            uint32_t a[4];
            LDMATRIX_X4(a[0], a[1], a[2], a[3],
                        base + OFF_A + aRow * PITCH_B + kOffB + aColB);
#pragma unroll
            for (int p = 0; p < 2; p++) {
                uint32_t bh0, bh1, bh2, bh3, bl0, bl1, bl2, bl3;
                uint32_t ba = base + (warpN + p * 16 + bRow) * PITCH_B + kOffB + bColB;
                LDMATRIX_X4(bh0, bh1, bh2, bh3, ba + OFF_BHI);
                LDMATRIX_X4(bl0, bl1, bl2, bl3, ba + OFF_BLO);
                MMA_FP16(C[2 * p],     a, bh0, bh1);
                MMA_FP16(C[2 * p],     a, bl0, bl1);
                MMA_FP16(C[2 * p + 1], a, bh2, bh3);
                MMA_FP16(C[2 * p + 1], a, bl2, bl3);
            }
        }
        if (++scur == 3) scur = 0;
    }

    const int g  = lane >> 2;
    const int q2 = (lane & 3) * 2;
    const int rowBase = ctaM + warpM;
#pragma unroll
    for (int nt = 0; nt < 4; nt++) {
        const int col = warpN + nt * 8 + q2;
        float2 bb = *(const float2*)(b3 + col);
        float2 v0, v1;
        v0.x = C[nt][0] + bb.x;
        v0.y = C[nt][1] + bb.y;
        v1.x = C[nt][2] + bb.x;
        v1.y = C[nt][3] + bb.y;
        *(float2*)(out + (size_t)(rowBase + g) * COUT + col) = v0;
        *(float2*)(out + (size_t)(rowBase + g + 8) * COUT + col) = v1;
    }
}

// ---------------------------------------------------------------------------
extern "C" void kernel_launch(void* const* d_in, const int* in_sizes, int n_in,
                              void* d_out, int out_size) {
    const float* x_in      = (const float*)d_in[0];
    const float* pos_in    = (const float*)d_in[1];
    const float* pos_out   = (const float*)d_in[2];
    const int*   in_index  = (const int*)d_in[3];
    const int*   out_index = (const int*)d_in[4];
    const float* W1        = (const float*)d_in[5];
    const float* W2        = (const float*)d_in[6];
    const float* W3        = (const float*)d_in[7];
    const float* b3        = (const float*)d_in[8];
    float* out = (float*)d_out;

    cudaFuncSetAttribute(gemm_mma, cudaFuncAttributeMaxDynamicSharedMemorySize, GEMM_SMEM);

    offsets_kernel<<<(NEDGE + 255) / 256, 256>>>(out_index);
    prep_w3_kernel<<<(1024 * 64) / 256, 256>>>(W3);
    edge_tc_kernel<<<NPTS / 4, 128>>>(x_in, pos_in, pos_out, in_index, W1, W2);
    gemm_mma<<<NPTS / 64, 256, GEMM_SMEM>>>(b3, out);
}

// round 9
// speedup vs baseline: 2.7532x; 1.0005x over previous
#include <cuda_runtime.h>
#include <cuda_bf16.h>
#include <cuda_fp16.h>
#include <math.h>
#include <stdint.h>

#define NPTS  32768
#define NEDGE 786432
#define CIN   16
#define CMID  64
#define COUT  64
#define KMAX  64

// ---------------- device scratch ----------------
__device__ __half g_P_h[(size_t)NPTS * 1024];
__device__ __half g_W3T_hi[COUT * 1024];
__device__ __half g_W3T_lo[COUT * 1024];
__device__ int g_start[NPTS + 1];

// branchless CELU: fmax(x,0) - 1 + exp(fmin(x,0))
__device__ __forceinline__ float celu_fast(float x) {
    return fmaxf(x, 0.0f) - 1.0f + __expf(fminf(x, 0.0f));
}
__device__ __forceinline__ uint32_t smem_u32(const void* p) {
    uint32_t a;
    asm("{ .reg .u64 t; cvta.to.shared.u64 t, %1; cvt.u32.u64 %0, t; }" : "=r"(a) : "l"(p));
    return a;
}
__device__ __forceinline__ void cp16(uint32_t dst, const void* src) {
    asm volatile("cp.async.cg.shared.global [%0], [%1], 16;" :: "r"(dst), "l"(src) : "memory");
}
#define CP_COMMIT() asm volatile("cp.async.commit_group;" ::: "memory")
#define CP_WAIT(n)  asm volatile("cp.async.wait_group %0;" :: "n"(n) : "memory")

#define LDMATRIX_X4(r0, r1, r2, r3, addr) \
    asm volatile("ldmatrix.sync.aligned.m8n8.x4.shared.b16 {%0,%1,%2,%3}, [%4];" \
                 : "=r"(r0), "=r"(r1), "=r"(r2), "=r"(r3) : "r"(addr))
#define LDMATRIX_X4_T(r0, r1, r2, r3, addr) \
    asm volatile("ldmatrix.sync.aligned.m8n8.x4.trans.shared.b16 {%0,%1,%2,%3}, [%4];" \
                 : "=r"(r0), "=r"(r1), "=r"(r2), "=r"(r3) : "r"(addr))

#define MMA_FP16(C, A, B0, B1) \
    asm volatile("mma.sync.aligned.m16n8k16.row.col.f32.f16.f16.f32 " \
        "{%0,%1,%2,%3}, {%4,%5,%6,%7}, {%8,%9}, {%0,%1,%2,%3};" \
        : "+f"((C)[0]), "+f"((C)[1]), "+f"((C)[2]), "+f"((C)[3]) \
        : "r"((A)[0]), "r"((A)[1]), "r"((A)[2]), "r"((A)[3]), "r"(B0), "r"(B1))

__device__ __forceinline__ uint32_t pack_half2(float a, float b) {
    __half2 h = __floats2half2_rn(a, b);
    return *(uint32_t*)&h;
}

// ---------------------------------------------------------------------------
// Kernel A: segment offsets
// ---------------------------------------------------------------------------
__global__ void offsets_kernel(const int* __restrict__ oi) {
    int e = blockIdx.x * 256 + threadIdx.x;
    if (e >= NEDGE) return;
    int v = oi[e];
    if (e == 0) {
        for (int n = 0; n <= v; n++) g_start[n] = 0;
    } else {
        int p = oi[e - 1];
        for (int n = p + 1; n <= v; n++) g_start[n] = e;
    }
    if (e == NEDGE - 1) {
        for (int n = v + 1; n <= NPTS; n++) g_start[n] = NEDGE;
    }
}

// ---------------------------------------------------------------------------
// Kernel B: W3 transpose + fp16 hi/lo split
// ---------------------------------------------------------------------------
__global__ void prep_w3_kernel(const float* __restrict__ W3) {
    int t = blockIdx.x * 256 + threadIdx.x;
    int k = t >> 6, n = t & 63;
    float v = W3[t];
    __half hi = __float2half_rn(v);
    __half lo = __float2half_rn(v - __half2float(hi));
    g_W3T_hi[n * 1024 + k] = hi;
    g_W3T_lo[n * 1024 + k] = lo;
}

// ---------------------------------------------------------------------------
// Kernel C: tensor-core edge kernel, fp16. Warp per point, 4 warps/CTA.
// Pair-interleaved tile phases: G1(t),G1(t+1) | sync | G2(t),G2(t+1).
// ---------------------------------------------------------------------------
#define PHP 48
#define PXP 144
#define PMP 144
#define WHP 48

__global__ __launch_bounds__(128) void edge_tc_kernel(
    const float* __restrict__ x_in,
    const float* __restrict__ pos_in,
    const float* __restrict__ pos_out,
    const int*   __restrict__ in_index,
    const float* __restrict__ W1,
    const float* __restrict__ W2)
{
    __shared__ __align__(16) float sW1[48];
    __shared__ __align__(16) char s_w2t[64 * WHP];
    __shared__ __align__(16) char s_h [4][64 * PHP];
    __shared__ __align__(16) char s_xT[4][16 * PXP];
    __shared__ __align__(16) char s_M [4][32 * PMP];   // 2 tiles

    const int tid  = threadIdx.x;
    const int warp = tid >> 5;
    const int lane = tid & 31;

    // ---- early loads before the CTA-wide smem sync ----
    const int n = blockIdx.x * 4 + warp;
    const int start = __ldg(g_start + n);
    const int cnt   = __ldg(g_start + n + 1) - start;
    const int nl    = cnt < KMAX ? cnt : KMAX;
    const int tiles = (nl + 15) >> 4;
    const float inv = (cnt > 0) ? (1.0f / (float)cnt) : 0.0f;

    const float po0 = __ldg(pos_out + 3 * n + 0);
    const float po1 = __ldg(pos_out + 3 * n + 1);
    const float po2 = __ldg(pos_out + 3 * n + 2);

    int myidx[2];
#pragma unroll
    for (int it = 0; it < 2; it++) {
        int e = lane + 32 * it;
        myidx[it] = (e < nl) ? __ldg(in_index + start + e) : -1;
    }

    // ---- CTA-shared weight staging ----
    if (tid < 48) sW1[tid] = W1[tid];
    for (int i = tid; i < 1024; i += 128) {
        int c = i >> 6, nn = i & 63;
        *(__half*)&s_w2t[nn * WHP + c * 2] = __float2half_rn(W2[i]);
    }
    __syncthreads();

    // hoist W2^T B-fragments
    uint32_t bW2[4][4];
    {
        uint32_t rsel = (uint32_t)((lane & 7) + ((lane & 16) ? 8 : 0));
        uint32_t csel = (lane & 8) ? 16u : 0u;
        uint32_t b0 = smem_u32(s_w2t);
#pragma unroll
        for (int j = 0; j < 4; j++) {
            uint32_t a = (rsel + j * 16) * WHP + csel;
            LDMATRIX_X4(bW2[j][0], bW2[j][1], bW2[j][2], bW2[j][3], b0 + a);
        }
    }

    float P[32];
#pragma unroll
    for (int i = 0; i < 32; i++) P[i] = 0.0f;

    const uint32_t shB = smem_u32(s_h[warp]);
    const uint32_t sxB = smem_u32(s_xT[warp]);
    const uint32_t smB = smem_u32(s_M[warp]);

    // ---- prologue: one lane per edge, branch-free both iterations ----
#pragma unroll
    for (int it = 0; it < 2; it++) {
        const int e = lane + 32 * it;
        float h[16], x[16];
        const int idx = myidx[it];
        if (idx >= 0) {
            float d0 = __ldg(pos_in + 3 * idx + 0) - po0;
            float d1 = __ldg(pos_in + 3 * idx + 1) - po1;
            float d2 = __ldg(pos_in + 3 * idx + 2) - po2;
            const float4* xr = (const float4*)(x_in + (size_t)idx * CIN);
            float4 v0 = __ldg(xr), v1 = __ldg(xr + 1), v2 = __ldg(xr + 2), v3 = __ldg(xr + 3);
#pragma unroll
            for (int c = 0; c < 16; c++) {
                float a = fmaf(d0, sW1[c], fmaf(d1, sW1[16 + c], d2 * sW1[32 + c]));
                h[c] = celu_fast(a);
            }
            x[0] = v0.x;  x[1] = v0.y;  x[2] = v0.z;  x[3] = v0.w;
            x[4] = v1.x;  x[5] = v1.y;  x[6] = v1.z;  x[7] = v1.w;
            x[8] = v2.x;  x[9] = v2.y;  x[10] = v2.z; x[11] = v2.w;
            x[12] = v3.x; x[13] = v3.y; x[14] = v3.z; x[15] = v3.w;
        } else {
#pragma unroll
            for (int c = 0; c < 16; c++) { h[c] = 0.0f; x[c] = 0.0f; }
        }
        uint32_t hp[8];
#pragma unroll
        for (int j = 0; j < 8; j++) hp[j] = pack_half2(h[2 * j], h[2 * j + 1]);
        *(uint4*)(s_h[warp] + (uint32_t)e * PHP)      = make_uint4(hp[0], hp[1], hp[2], hp[3]);
        *(uint4*)(s_h[warp] + (uint32_t)e * PHP + 16) = make_uint4(hp[4], hp[5], hp[6], hp[7]);
#pragma unroll
        for (int c = 0; c < 16; c++) {
            *(__half*)(s_xT[warp] + (uint32_t)c * PXP + e * 2) = __float2half_rn(x[c]);
        }
    }
    __syncwarp();

    const uint32_t aRowOff = (uint32_t)(lane & 15);
    const uint32_t aColB   = ((lane >> 4) & 1) * 16;
    const uint32_t tRow    = (uint32_t)((lane & 7) + (((lane >> 3) & 1) << 3));
    const uint32_t tCol    = ((lane >> 4) & 1) * 16;
    const int g = lane >> 2;
    const int q = lane & 3;

    // GEMM1 for one tile into s_M slot
    auto gemm1 = [&](int t, int slot) {
        uint32_t a[4];
        LDMATRIX_X4(a[0], a[1], a[2], a[3],
                    shB + (t * 16 + aRowOff) * PHP + aColB);
#pragma unroll
        for (int j = 0; j < 4; j++) {
#pragma unroll
            for (int sub = 0; sub < 2; sub++) {
                const int nt = 2 * j + sub;
                float C1[4] = {0.f, 0.f, 0.f, 0.f};
                MMA_FP16(C1, a, bW2[j][2 * sub], bW2[j][2 * sub + 1]);
                const uint32_t cb = (uint32_t)(nt * 16 + q * 4);
#pragma unroll
                for (int r2 = 0; r2 < 2; r2++) {
                    float v0 = celu_fast(C1[2 * r2]);
                    float v1 = celu_fast(C1[2 * r2 + 1]);
                    *(uint32_t*)(s_M[warp] + (uint32_t)(slot * 16 + g + 8 * r2) * PMP + cb) =
                        pack_half2(v0, v1);
                }
            }
        }
    };
    // GEMM2 for one tile from s_M slot
    auto gemm2 = [&](int t, int slot) {
        uint32_t ax[4];
        LDMATRIX_X4(ax[0], ax[1], ax[2], ax[3],
                    sxB + aRowOff * PXP + t * 32 + aColB);
#pragma unroll
        for (int pp = 0; pp < 4; pp++) {
            uint32_t b0, b1, b2, b3;
            LDMATRIX_X4_T(b0, b1, b2, b3,
                          smB + (slot * 16 + tRow) * PMP + pp * 32 + tCol);
            MMA_FP16(P + (2 * pp) * 4,     ax, b0, b1);
            MMA_FP16(P + (2 * pp + 1) * 4, ax, b2, b3);
        }
    };

    for (int t = 0; t < tiles; t += 2) {
        const bool two = (t + 1 < tiles);
        gemm1(t, 0);
        if (two) gemm1(t + 1, 1);
        __syncwarp();
        gemm2(t, 0);
        if (two) gemm2(t + 1, 1);
        __syncwarp();
    }

    // ---- store P * inv (fp16) ----
    __half* dp = g_P_h + (size_t)n * 1024;
#pragma unroll
    for (int nt = 0; nt < 8; nt++) {
#pragma unroll
        for (int r2 = 0; r2 < 2; r2++) {
            int c = g + 8 * r2;
            int m = nt * 8 + 2 * q;
            *(uint32_t*)(dp + c * 64 + m) =
                pack_half2(P[nt * 4 + 2 * r2] * inv, P[nt * 4 + 2 * r2 + 1] * inv);
        }
    }
}

// ---------------------------------------------------------------------------
// Kernel D: out = P @ W3 + b3. M=128/CTA, 256 thr, 3-stage (R7 proven config).
// ---------------------------------------------------------------------------
#define PITCH_B 80
#define OFF_A   0
#define OFF_BHI 10240
#define OFF_BLO 15360
#define STAGE_BYTES 20480
#define GEMM_SMEM (3 * STAGE_BYTES)

__global__ __launch_bounds__(256) void gemm_mma(
    const float* __restrict__ b3,
    float* __restrict__ out)
{
    extern __shared__ char dsm[];
    const uint32_t sbase = smem_u32(dsm);

    const int tid  = threadIdx.x;
    const int warp = tid >> 5;
    const int lane = tid & 31;
    const int ctaM = blockIdx.x * 128;

    const char* A_g   = (const char*)(g_P_h + (size_t)ctaM * 1024);
    const char* Bhi_g = (const char*)g_W3T_hi;
    const char* Blo_g = (const char*)g_W3T_lo;

    auto issue_loads = [&](int kt, int s) {
        uint32_t base = sbase + s * STAGE_BYTES;
        const int kb = kt * 64;
#pragma unroll
        for (int i = 0; i < 2; i++) {
            int idx = tid + i * 256;
            int row = idx >> 2, seg = idx & 3;
            uint32_t d = base + OFF_A + row * PITCH_B + seg * 16;
            cp16(d, A_g + (size_t)row * 2048 + kb + seg * 16);
        }
        {
            int row = tid >> 2, seg = tid & 3;
            uint32_t d = base + row * PITCH_B + seg * 16;
            size_t gofs = (size_t)row * 2048 + kb + seg * 16;
            cp16(d + OFF_BHI, Bhi_g + gofs);
            cp16(d + OFF_BLO, Blo_g + gofs);
        }
    };

    float C[8][4];
#pragma unroll
    for (int nt = 0; nt < 8; nt++)
#pragma unroll
        for (int i = 0; i < 4; i++) C[nt][i] = 0.0f;

    const uint32_t aRow  = warp * 16 + (lane & 15);
    const uint32_t aColB = ((lane >> 4) & 1) * 16;
    const uint32_t bRow  = (lane & 7) + ((lane & 16) ? 8 : 0);
    const uint32_t bColB = (lane & 8) ? 16 : 0;

    issue_loads(0, 0); CP_COMMIT();
    issue_loads(1, 1); CP_COMMIT();

    int scur = 0;
    for (int kt = 0; kt < 32; kt++) {
        CP_WAIT(1);
        __syncthreads();
        if (kt + 2 < 32) {
            int snext = scur + 2; if (snext >= 3) snext -= 3;
            issue_loads(kt + 2, snext);
        }
        CP_COMMIT();

        const uint32_t base = sbase + scur * STAGE_BYTES;
#pragma unroll
        for (int ks = 0; ks < 2; ks++) {
            const uint32_t kOffB = ks * 32;
            uint32_t a[4];
            LDMATRIX_X4(a[0], a[1], a[2], a[3],
                        base + OFF_A + aRow * PITCH_B + kOffB + aColB);
#pragma unroll
            for (int p = 0; p < 4; p++) {
                uint32_t bh0, bh1, bh2, bh3, bl0, bl1, bl2, bl3;
                uint32_t ba = base + (p * 16 + bRow) * PITCH_B + kOffB + bColB;
                LDMATRIX_X4(bh0, bh1, bh2, bh3, ba + OFF_BHI);
                LDMATRIX_X4(bl0, bl1, bl2, bl3, ba + OFF_BLO);
                MMA_FP16(C[2 * p],     a, bh0, bh1);
                MMA_FP16(C[2 * p],     a, bl0, bl1);
                MMA_FP16(C[2 * p + 1], a, bh2, bh3);
                MMA_FP16(C[2 * p + 1], a, bl2, bl3);
            }
        }
        if (++scur == 3) scur = 0;
    }

    const int g  = lane >> 2;
    const int q2 = (lane & 3) * 2;
    const int rowBase = ctaM + warp * 16;
#pragma unroll
    for (int nt = 0; nt < 8; nt++) {
        const int col = nt * 8 + q2;
        float2 bb = *(const float2*)(b3 + col);
        float2 v0, v1;
        v0.x = C[nt][0] + bb.x;
        v0.y = C[nt][1] + bb.y;
        v1.x = C[nt][2] + bb.x;
        v1.y = C[nt][3] + bb.y;
        *(float2*)(out + (size_t)(rowBase + g) * COUT + col) = v0;
        *(float2*)(out + (size_t)(rowBase + g + 8) * COUT + col) = v1;
    }
}

// ---------------------------------------------------------------------------
extern "C" void kernel_launch(void* const* d_in, const int* in_sizes, int n_in,
                              void* d_out, int out_size) {
    const float* x_in      = (const float*)d_in[0];
    const float* pos_in    = (const float*)d_in[1];
    const float* pos_out   = (const float*)d_in[2];
    const int*   in_index  = (const int*)d_in[3];
    const int*   out_index = (const int*)d_in[4];
    const float* W1        = (const float*)d_in[5];
    const float* W2        = (const float*)d_in[6];
    const float* W3        = (const float*)d_in[7];
    const float* b3        = (const float*)d_in[8];
    float* out = (float*)d_out;

    cudaFuncSetAttribute(gemm_mma, cudaFuncAttributeMaxDynamicSharedMemorySize, GEMM_SMEM);

    offsets_kernel<<<(NEDGE + 255) / 256, 256>>>(out_index);
    prep_w3_kernel<<<(1024 * 64) / 256, 256>>>(W3);
    edge_tc_kernel<<<NPTS / 4, 128>>>(x_in, pos_in, pos_out, in_index, W1, W2);
    gemm_mma<<<NPTS / 128, 256, GEMM_SMEM>>>(b3, out);
}